// round 12
// baseline (speedup 1.0000x reference)
#include <cuda_runtime.h>
#include <math.h>
#include <stdint.h>

#define NN 4096
#define KK 32
#define DD 256
#define HH 128
#define GG 384   // 3*H

typedef unsigned long long ull;

// ---------------- scratch (__device__ globals, no allocation) ----------------
__device__ int    g_order[NN];
__device__ int    g_len[KK];
__device__ int    g_off[KK];
__device__ float4 g_Wih0T[(DD/4)*GG];
__device__ float  g_xw0[NN*GG];
__device__ float  g_cemb[KK*HH];
__device__ float  g_scores[NN];

// ---------------- PTX helpers ------------------------------------------------
__device__ __forceinline__ uint32_t smem_u32(const void* p) {
    uint32_t a;
    asm("{ .reg .u64 t; cvta.to.shared.u64 t, %1; cvt.u32.u64 %0, t; }"
        : "=r"(a) : "l"(p));
    return a;
}
__device__ __forceinline__ uint32_t mapa_rank(uint32_t laddr, int rank) {
    uint32_t r;
    asm("mapa.shared::cluster.u32 %0, %1, %2;" : "=r"(r) : "r"(laddr), "r"(rank));
    return r;
}
__device__ __forceinline__ void st_async_pre(uint32_t raddr, uint32_t rmbar, float v) {
    uint32_t b = __float_as_uint(v);
    asm volatile("st.async.shared::cluster.mbarrier::complete_tx::bytes.b32 [%0], %1, [%2];"
                 :: "r"(raddr), "r"(b), "r"(rmbar) : "memory");
}
__device__ __forceinline__ void rearm_bar(uint32_t mbar, uint32_t txbytes) {
    asm volatile("mbarrier.arrive.expect_tx.shared::cta.b64 _, [%0], %1;"
                 :: "r"(mbar), "r"(txbytes) : "memory");
}
__device__ __forceinline__ void arrive_remote(uint32_t raddr) {
    asm volatile("mbarrier.arrive.release.cluster.shared::cluster.b64 _, [%0];"
                 :: "r"(raddr) : "memory");
}
__device__ __forceinline__ void mbar_init(uint32_t mbar, uint32_t cnt) {
    asm volatile("mbarrier.init.shared.b64 [%0], %1;" :: "r"(mbar), "r"(cnt) : "memory");
}
__device__ __forceinline__ void wait_bar(uint32_t mbar, uint32_t parity) {
    asm volatile(
        "{\n\t.reg .pred P;\n\t"
        "LW%=:\n\t"
        "mbarrier.try_wait.parity.acquire.cta.shared::cta.b64 P, [%0], %1;\n\t"
        "@!P bra LW%=;\n\t}"
        :: "r"(mbar), "r"(parity) : "memory");
}
__device__ __forceinline__ void fma2(ull& d, ull a, ull b) {
    asm("fma.rn.f32x2 %0, %1, %2, %0;" : "+l"(d) : "l"(a), "l"(b));
}
__device__ __forceinline__ float2 unpk(ull v) {
    float2 r;
    asm("mov.b64 {%0, %1}, %2;" : "=f"(r.x), "=f"(r.y) : "l"(v));
    return r;
}
__device__ __forceinline__ float tanha(float x) {
    float y;
    asm("tanh.approx.f32 %0, %1;" : "=f"(y) : "f"(x));
    return y;
}
__device__ __forceinline__ float siga(float x) {
    return fmaf(0.5f, tanha(0.5f * x), 0.5f);
}

// ---------------- K0: fused transpose (blocks 0..23) + order (block 24) -----
__global__ __launch_bounds__(1024) void k_prep(const float* __restrict__ W_ih0,
                                               const int* __restrict__ labels) {
    if (blockIdx.x < 24) {
        int idx = blockIdx.x * 1024 + threadIdx.x;
        int k4 = idx & 63;
        int g  = idx >> 6;
        float4 v = *reinterpret_cast<const float4*>(W_ih0 + g * DD + 4 * k4);
        g_Wih0T[k4 * GG + g] = v;
        return;
    }
    __shared__ int slab[NN];
    __shared__ int s_len[KK];
    __shared__ int s_off[KK];
    int tid = threadIdx.x;
    int c    = tid >> 5;
    int lane = tid & 31;

#pragma unroll
    for (int r = 0; r < NN / 1024; r++)
        slab[r * 1024 + tid] = labels[r * 1024 + tid];
    __syncthreads();

    int count = 0;
    for (int base = 0; base < NN; base += 32) {
        int lab = slab[base + lane];
        unsigned m = __ballot_sync(0xffffffffu, lab == c);
        count += __popc(m);
    }
    if (lane == 0) s_len[c] = count;
    __syncthreads();

    if (c == 0) {
        int len = s_len[lane];
        int off = 0;
        for (int j = 0; j < KK; j++) {
            int lj = __shfl_sync(0xffffffffu, len, j);
            if (j < lane) off += lj;
        }
        s_off[lane] = off;
        g_len[lane] = len;
        g_off[lane] = off;
    }
    __syncthreads();

    int off = s_off[c];
    int cnt = 0;
    for (int base = 0; base < NN; base += 32) {
        int lab = slab[base + lane];
        unsigned m = __ballot_sync(0xffffffffu, lab == c);
        if (lab == c) {
            int p = cnt + __popc(m & ((1u << lane) - 1u));
            g_order[off + p] = base + lane;
        }
        cnt += __popc(m);
    }
}

// ---------------- K2: xw0 = X_gathered @ W_ih0^T + b_ih0 (f32x2) ------------
#define TS 16
__global__ __launch_bounds__(GG) void k_xw0(const float* __restrict__ x,
                                            const float* __restrict__ b_ih0) {
    __shared__ __align__(16) float shx[TS * DD];
    int g  = threadIdx.x;
    int s0 = blockIdx.x * TS;

    for (int idx = g; idx < TS * DD; idx += GG) {
        int s2 = idx / DD;
        int kk = idx % DD;
        int sent = g_order[s0 + s2];
        shx[idx] = x[sent * DD + kk];
    }
    __syncthreads();

    ull a01[TS], a23[TS];
#pragma unroll
    for (int i = 0; i < TS; i++) { a01[i] = 0ull; a23[i] = 0ull; }

    const ulonglong2* W2 = reinterpret_cast<const ulonglong2*>(g_Wih0T);
    for (int k4 = 0; k4 < DD / 4; k4++) {
        ulonglong2 w = W2[k4 * GG + g];
#pragma unroll
        for (int s2 = 0; s2 < TS; s2++) {
            ulonglong2 xv = *reinterpret_cast<const ulonglong2*>(&shx[s2 * DD + 4 * k4]);
            fma2(a01[s2], w.x, xv.x);
            fma2(a23[s2], w.y, xv.y);
        }
    }
    float b = b_ih0[g];
#pragma unroll
    for (int s2 = 0; s2 < TS; s2++) {
        float2 p = unpk(a01[s2]), q = unpk(a23[s2]);
        g_xw0[(s0 + s2) * GG + g] = (p.x + p.y) + (q.x + q.y) + b;
    }
}

// ---------------- K3: pipelined GRU: 4-CTA cluster = {L0, IH1a, IH1b, L1} ----
// rank0 (A):  full layer-0 recurrence, h1 local; streams h1[s] to ranks 1,2.
// rank1/2:    xw1 = W_ih1 @ h1[s] (feed-forward, 192 rows each) -> stream to 3.
// rank3 (C):  full layer-1 recurrence (W_hh1 local) + gates; h2 local.
// Rings: depth 2, slot=s&1, phase parity=(s>>1)&1. Data barriers tx-armed by
// consumer 2 phases ahead; credits are count-based remote arrives (suppressed
// on the last 2 steps so nothing is in flight at exit).
__global__ __launch_bounds__(GG, 1) __cluster_dims__(4, 1, 1)
void k_gru(const float* __restrict__ W_hh0, const float* __restrict__ W_ih1,
           const float* __restrict__ W_hh1,
           const float* __restrict__ b_ih0, const float* __restrict__ b_hh0,
           const float* __restrict__ b_ih1, const float* __restrict__ b_hh1) {
    struct __align__(16) SM {
        float h1buf[2][HH];   // A: h1 double buf ; B1x: h1 ring
        float big[2][GG];     // C: xw1 ring
        float sums[GG];       // A / C: row sums
        float h2buf[2][HH];   // C: h2 double buf
        unsigned long long mbar[4];  // [0,1]=full(slot) [2,3]=credit(slot)
    };
    __shared__ SM sm;

    int t = threadIdx.x, w = t >> 5, l = t & 31;
    int rank = blockIdx.x & 3;
    int c    = blockIdx.x >> 2;

    uint32_t mb    = smem_u32(&sm.mbar[0]);
    uint32_t ringA = smem_u32(&sm.h1buf[0][0]);
    uint32_t ringC = smem_u32(&sm.big[0][0]);

    if (t == 0) {
        mbar_init(mb + 0, 1);  mbar_init(mb + 8, 1);
        uint32_t cc = (rank == 0) ? 2u : 1u;
        mbar_init(mb + 16, cc); mbar_init(mb + 24, cc);
        if (rank == 1 || rank == 2) { rearm_bar(mb + 0, 512);  rearm_bar(mb + 8, 512); }
        if (rank == 3)              { rearm_bar(mb + 0, 1536); rearm_bar(mb + 8, 1536); }
    }
    if (t < HH) {
        sm.h1buf[0][t] = 0.f; sm.h1buf[1][t] = 0.f;
        sm.h2buf[0][t] = 0.f; sm.h2buf[1][t] = 0.f;
    }
    asm volatile("fence.proxy.async.shared::cta;" ::: "memory");
    __syncthreads();
    asm volatile("barrier.cluster.arrive.aligned;" ::: "memory");
    asm volatile("barrier.cluster.wait.aligned;" ::: "memory");

    int len = g_len[c], off = g_off[c];
    int steps = len > 0 ? len : 1;

    if (rank == 0) {
        // ================= stage A: layer-0 recurrence =================
        ulonglong2 wv[32];
        const ulonglong2* wp = reinterpret_cast<const ulonglong2*>(W_hh0 + t * HH);
#pragma unroll
        for (int j = 0; j < 32; j++) wv[j] = wp[j];
        float bir = 0, biz = 0, bin = 0, bhr = 0, bhz = 0, bhn = 0;
        if (t < HH) {
            bir = b_ih0[t]; biz = b_ih0[t + 128]; bin = b_ih0[t + 256];
            bhr = b_hh0[t]; bhz = b_hh0[t + 128]; bhn = b_hh0[t + 256];
        }
        uint32_t r1r = mapa_rank(ringA, 1), r1b = mapa_rank(mb, 1);
        uint32_t r2r = mapa_rank(ringA, 2), r2b = mapa_rank(mb, 2);

        for (int s = 0; s < steps; s++) {
            float xwr = bir, xwz = biz, xwn = bin;
            if (t < HH && s < len) {
                const float* xp = g_xw0 + (off + s) * GG + t;
                xwr = xp[0]; xwz = xp[128]; xwn = xp[256];
            }
            if (s >= 2) wait_bar(mb + 16 + (s & 1) * 8, (uint32_t)(((s - 2) >> 1) & 1));

            const ulonglong2* hv = reinterpret_cast<const ulonglong2*>(&sm.h1buf[(s + 1) & 1][0]);
            ull a0 = 0, a1 = 0, a2 = 0, a3 = 0;
#pragma unroll
            for (int j = 0; j < 32; j += 2) {
                ulonglong2 h = hv[j];
                fma2(a0, wv[j].x, h.x); fma2(a1, wv[j].y, h.y);
                ulonglong2 h2 = hv[j + 1];
                fma2(a2, wv[j + 1].x, h2.x); fma2(a3, wv[j + 1].y, h2.y);
            }
            float2 p = unpk(a0), q = unpk(a1), r2 = unpk(a2), u = unpk(a3);
            sm.sums[t] = ((p.x + p.y) + (q.x + q.y)) + ((r2.x + r2.y) + (u.x + u.y));
            __syncthreads();

            if (t < HH) {
                float hr = sm.sums[t] + bhr;
                float hz = sm.sums[128 + t] + bhz;
                float hn = sm.sums[256 + t] + bhn;
                float rg = siga(xwr + hr);
                float zg = siga(xwz + hz);
                float ng = tanha(xwn + rg * hn);
                float h1n = (1.f - zg) * ng + zg * sm.h1buf[(s + 1) & 1][t];
                sm.h1buf[s & 1][t] = h1n;
                uint32_t o4 = (uint32_t)(((s & 1) * HH + t) * 4);
                uint32_t bo = (uint32_t)((s & 1) * 8);
                st_async_pre(r1r + o4, r1b + bo, h1n);
                st_async_pre(r2r + o4, r2b + bo, h1n);
            }
            __syncthreads();
        }
    } else if (rank == 3) {
        // ================= stage C: layer-1 recurrence + gates =================
        ulonglong2 wv[32];
        const ulonglong2* wp = reinterpret_cast<const ulonglong2*>(W_hh1 + t * HH);
#pragma unroll
        for (int j = 0; j < 32; j++) wv[j] = wp[j];
        float bir = 0, biz = 0, bin = 0, bhr = 0, bhz = 0, bhn = 0;
        if (t < HH) {
            bir = b_ih1[t]; biz = b_ih1[t + 128]; bin = b_ih1[t + 256];
            bhr = b_hh1[t]; bhz = b_hh1[t + 128]; bhn = b_hh1[t + 256];
        }
        uint32_t rB1 = mapa_rank(mb, 1), rB2 = mapa_rank(mb, 2);
        float h2fin = 0.f;

        for (int s = 0; s < steps; s++) {
            const ulonglong2* hv = reinterpret_cast<const ulonglong2*>(&sm.h2buf[(s + 1) & 1][0]);
            ull a0 = 0, a1 = 0, a2 = 0, a3 = 0;
#pragma unroll
            for (int j = 0; j < 32; j += 2) {
                ulonglong2 h = hv[j];
                fma2(a0, wv[j].x, h.x); fma2(a1, wv[j].y, h.y);
                ulonglong2 h2 = hv[j + 1];
                fma2(a2, wv[j + 1].x, h2.x); fma2(a3, wv[j + 1].y, h2.y);
            }
            float2 p = unpk(a0), q = unpk(a1), r2 = unpk(a2), u = unpk(a3);
            sm.sums[t] = ((p.x + p.y) + (q.x + q.y)) + ((r2.x + r2.y) + (u.x + u.y));

            wait_bar(mb + (s & 1) * 8, (uint32_t)((s >> 1) & 1));   // xw1 ready
            __syncthreads();

            if (t < HH) {
                float xr = sm.big[s & 1][t]       + bir;
                float xz = sm.big[s & 1][128 + t] + biz;
                float xn = sm.big[s & 1][256 + t] + bin;
                float hr = sm.sums[t]       + bhr;
                float hz = sm.sums[128 + t] + bhz;
                float hn = sm.sums[256 + t] + bhn;
                float rg = siga(xr + hr);
                float zg = siga(xz + hz);
                float ng = tanha(xn + rg * hn);
                float h2n = (1.f - zg) * ng + zg * sm.h2buf[(s + 1) & 1][t];
                sm.h2buf[s & 1][t] = h2n;
                if (s == steps - 1) h2fin = h2n;
            }
            __syncthreads();
            if (t == 0) {
                rearm_bar(mb + (s & 1) * 8, 1536);
                if (s < steps - 2) {
                    arrive_remote(rB1 + 16 + (uint32_t)((s & 1) * 8));
                    arrive_remote(rB2 + 16 + (uint32_t)((s & 1) * 8));
                }
            }
        }
        if (t < HH) g_cemb[c * HH + t] = h2fin;
    } else {
        // ================= stage B: xw1 feed-forward (192 rows) =================
        int base = (rank - 1) * 192;
        int rloc = w * 16 + (l & 15);
        int hf   = l >> 4;
        const ulonglong2* wp =
            reinterpret_cast<const ulonglong2*>(W_ih1 + (base + rloc) * HH + 64 * hf);
        ulonglong2 wv[16];
#pragma unroll
        for (int j = 0; j < 16; j++) wv[j] = wp[j];
        uint32_t rcr = mapa_rank(ringC, 3), rcb = mapa_rank(mb, 3);
        uint32_t rAc = mapa_rank(mb, 0);

        for (int s = 0; s < steps; s++) {
            wait_bar(mb + (s & 1) * 8, (uint32_t)((s >> 1) & 1));   // h1 ready
            const ulonglong2* hv =
                reinterpret_cast<const ulonglong2*>(&sm.h1buf[s & 1][64 * hf]);
            ull a0 = 0, a1 = 0;
#pragma unroll
            for (int j = 0; j < 16; j++) {
                ulonglong2 h = hv[j];
                fma2(a0, wv[j].x, h.x); fma2(a1, wv[j].y, h.y);
            }
            float2 p = unpk(a0), q = unpk(a1);
            float v = (p.x + p.y) + (q.x + q.y);
            v += __shfl_xor_sync(0xffffffffu, v, 16);

            if (s >= 2) wait_bar(mb + 16 + (s & 1) * 8, (uint32_t)(((s - 2) >> 1) & 1));
            if (l < 16)
                st_async_pre(rcr + (uint32_t)(((s & 1) * GG + base + rloc) * 4),
                             rcb + (uint32_t)((s & 1) * 8), v);
            __syncthreads();
            if (t == 0) {
                rearm_bar(mb + (s & 1) * 8, 512);
                if (s < steps - 2) arrive_remote(rAc + 16 + (uint32_t)((s & 1) * 8));
            }
        }
    }

    asm volatile("barrier.cluster.arrive.aligned;" ::: "memory");
    asm volatile("barrier.cluster.wait.aligned;" ::: "memory");
}

// ---------------- K4: per-sentence scores (wn + cscore computed in-block) ----
__global__ __launch_bounds__(512) void k_score(const float* __restrict__ x,
                                               const int* __restrict__ labels,
                                               const float* __restrict__ lin_v,
                                               const float* __restrict__ lin_g,
                                               const float* __restrict__ lin_b) {
    __shared__ float swn[GG];
    __shared__ float red[16];
    __shared__ float scs[KK];
    int t = threadIdx.x;
    int warp = t >> 5, lane = t & 31;

    float v = (t < GG) ? lin_v[t] : 0.f;
    float sq = v * v;
    for (int o = 16; o > 0; o >>= 1) sq += __shfl_xor_sync(0xffffffffu, sq, o);
    if (lane == 0) red[warp] = sq;
    __syncthreads();
    if (t == 0) {
        float s = 0.f;
#pragma unroll
        for (int i = 0; i < 16; i++) s += red[i];
        red[0] = 1.f / sqrtf(s);
    }
    __syncthreads();
    if (t < GG) swn[t] = lin_g[0] * v * red[0];
    __syncthreads();

#pragma unroll
    for (int j = 0; j < 2; j++) {
        int c = warp * 2 + j;
        float s = 0.f;
#pragma unroll
        for (int q = 0; q < HH / 32; q++)
            s += g_cemb[c * HH + q * 32 + lane] * swn[DD + q * 32 + lane];
        for (int o = 16; o > 0; o >>= 1) s += __shfl_xor_sync(0xffffffffu, s, o);
        if (lane == 0) scs[c] = s;
    }
    __syncthreads();

    int i = blockIdx.x * 16 + warp;
    const float* xr = x + i * DD;
    float s = 0.f;
#pragma unroll
    for (int q = 0; q < DD / 32; q++)
        s += xr[q * 32 + lane] * swn[q * 32 + lane];
    for (int o = 16; o > 0; o >>= 1) s += __shfl_xor_sync(0xffffffffu, s, o);
    if (lane == 0)
        g_scores[i] = tanhf(s + scs[labels[i]] + lin_b[0]);
}

// ---------------- K5: segment sum + final combine ----------------------------
__global__ void k_tail(const int* __restrict__ labels, float* __restrict__ out) {
    __shared__ float s_sum[KK];
    __shared__ int   slab[NN];
    __shared__ float ssc[NN];
    int tid = threadIdx.x;
#pragma unroll
    for (int r = 0; r < NN / 1024; r++) {
        slab[r * 1024 + tid] = labels[r * 1024 + tid];
        ssc[r * 1024 + tid]  = g_scores[r * 1024 + tid];
    }
    __syncthreads();

    int c = tid >> 5, lane = tid & 31;
    float s = 0.f;
    for (int base = 0; base < NN; base += 32) {
        int lab = slab[base + lane];
        float v = ssc[base + lane];
        if (lab == c) s += v;
    }
    for (int o = 16; o > 0; o >>= 1) s += __shfl_xor_sync(0xffffffffu, s, o);
    if (lane == 0) s_sum[c] = s;
    __syncthreads();

#pragma unroll
    for (int r = 0; r < NN / 1024; r++) {
        int i = r * 1024 + tid;
        float sal = ssc[i] / s_sum[slab[i]];
        float p = fmaxf(0.5f, expf(-(float)(i + 1) * 0.0625f));  // 1/4096^(1/3)=1/16
        out[i] = 0.5f * sal + 0.5f * p;
    }
}

// ---------------- launch ------------------------------------------------------
extern "C" void kernel_launch(void* const* d_in, const int* in_sizes, int n_in,
                              void* d_out, int out_size) {
    const float* x     = (const float*)d_in[0];
    const int*   labels= (const int*)  d_in[1];
    const float* W_ih0 = (const float*)d_in[2];
    const float* W_hh0 = (const float*)d_in[3];
    const float* b_ih0 = (const float*)d_in[4];
    const float* b_hh0 = (const float*)d_in[5];
    const float* W_ih1 = (const float*)d_in[6];
    const float* W_hh1 = (const float*)d_in[7];
    const float* b_ih1 = (const float*)d_in[8];
    const float* b_hh1 = (const float*)d_in[9];
    const float* lin_v = (const float*)d_in[10];
    const float* lin_g = (const float*)d_in[11];
    const float* lin_b = (const float*)d_in[12];
    float* out = (float*)d_out;

    k_prep<<<25, 1024>>>(W_ih0, labels);
    k_xw0<<<NN / TS, GG>>>(x, b_ih0);
    k_gru<<<KK * 4, GG>>>(W_hh0, W_ih1, W_hh1, b_ih0, b_hh0, b_ih1, b_hh1);
    k_score<<<NN / 16, 512>>>(x, labels, lin_v, lin_g, lin_b);
    k_tail<<<1, 1024>>>(labels, out);
}

// round 13
// speedup vs baseline: 1.1060x; 1.1060x over previous
#include <cuda_runtime.h>
#include <math.h>
#include <stdint.h>

#define NN 4096
#define KK 32
#define DD 256
#define HH 128
#define GG 384   // 3*H
#define SUBS 4   // CTAs per cluster-sequence

typedef unsigned long long ull;

// ---------------- scratch (__device__ globals, no allocation) ----------------
__device__ int    g_order[NN];
__device__ int    g_len[KK];
__device__ int    g_off[KK];
__device__ float4 g_Wih0T[(DD/4)*GG];
__device__ float  g_xw0[NN*GG];
__device__ float  g_cemb[KK*HH];
__device__ float  g_scores[NN];

// ---------------- PTX helpers ------------------------------------------------
__device__ __forceinline__ uint32_t smem_u32(const void* p) {
    uint32_t a;
    asm("{ .reg .u64 t; cvta.to.shared.u64 t, %1; cvt.u32.u64 %0, t; }"
        : "=r"(a) : "l"(p));
    return a;
}
__device__ __forceinline__ uint32_t mapa_rank(uint32_t laddr, int rank) {
    uint32_t r;
    asm("mapa.shared::cluster.u32 %0, %1, %2;" : "=r"(r) : "r"(laddr), "r"(rank));
    return r;
}
__device__ __forceinline__ void st_async_pre(uint32_t raddr, uint32_t rmbar, float v) {
    uint32_t b = __float_as_uint(v);
    asm volatile("st.async.shared::cluster.mbarrier::complete_tx::bytes.b32 [%0], %1, [%2];"
                 :: "r"(raddr), "r"(b), "r"(rmbar) : "memory");
}
__device__ __forceinline__ void rearm_bar(uint32_t mbar, uint32_t txbytes) {
    asm volatile("mbarrier.arrive.expect_tx.shared::cta.b64 _, [%0], %1;"
                 :: "r"(mbar), "r"(txbytes) : "memory");
}
__device__ __forceinline__ void wait_bar(uint32_t mbar, uint32_t parity) {
    asm volatile(
        "{\n\t.reg .pred P;\n\t"
        "LW%=:\n\t"
        "mbarrier.try_wait.parity.acquire.cta.shared::cta.b64 P, [%0], %1;\n\t"
        "@!P bra LW%=;\n\t}"
        :: "r"(mbar), "r"(parity) : "memory");
}
__device__ __forceinline__ void fma2(ull& d, ull a, ull b) {
    asm("fma.rn.f32x2 %0, %1, %2, %0;" : "+l"(d) : "l"(a), "l"(b));
}
__device__ __forceinline__ float2 unpk(ull v) {
    float2 r;
    asm("mov.b64 {%0, %1}, %2;" : "=f"(r.x), "=f"(r.y) : "l"(v));
    return r;
}
__device__ __forceinline__ float tanha(float x) {
    float y;
    asm("tanh.approx.f32 %0, %1;" : "=f"(y) : "f"(x));
    return y;
}
__device__ __forceinline__ float siga(float x) {
    return fmaf(0.5f, tanha(0.5f * x), 0.5f);
}

// ---------------- K0: fused transpose (blocks 0..23) + order (block 24) -----
__global__ __launch_bounds__(1024) void k_prep(const float* __restrict__ W_ih0,
                                               const int* __restrict__ labels) {
    if (blockIdx.x < 24) {
        int idx = blockIdx.x * 1024 + threadIdx.x;
        int k4 = idx & 63;
        int g  = idx >> 6;
        float4 v = *reinterpret_cast<const float4*>(W_ih0 + g * DD + 4 * k4);
        g_Wih0T[k4 * GG + g] = v;
        return;
    }
    __shared__ int slab[NN];
    __shared__ int s_len[KK];
    __shared__ int s_off[KK];
    int tid = threadIdx.x;
    int c    = tid >> 5;
    int lane = tid & 31;

#pragma unroll
    for (int r = 0; r < NN / 1024; r++)
        slab[r * 1024 + tid] = labels[r * 1024 + tid];
    __syncthreads();

    int count = 0;
    for (int base = 0; base < NN; base += 32) {
        int lab = slab[base + lane];
        unsigned m = __ballot_sync(0xffffffffu, lab == c);
        count += __popc(m);
    }
    if (lane == 0) s_len[c] = count;
    __syncthreads();

    if (c == 0) {
        int len = s_len[lane];
        int off = 0;
        for (int j = 0; j < KK; j++) {
            int lj = __shfl_sync(0xffffffffu, len, j);
            if (j < lane) off += lj;
        }
        s_off[lane] = off;
        g_len[lane] = len;
        g_off[lane] = off;
    }
    __syncthreads();

    int off = s_off[c];
    int cnt = 0;
    for (int base = 0; base < NN; base += 32) {
        int lab = slab[base + lane];
        unsigned m = __ballot_sync(0xffffffffu, lab == c);
        if (lab == c) {
            int p = cnt + __popc(m & ((1u << lane) - 1u));
            g_order[off + p] = base + lane;
        }
        cnt += __popc(m);
    }
}

// ---------------- K2: xw0 = X_gathered @ W_ih0^T + b_ih0 (f32x2, TS=32) -----
#define TS 32
__global__ __launch_bounds__(GG) void k_xw0(const float* __restrict__ x,
                                            const float* __restrict__ b_ih0) {
    __shared__ __align__(16) float shx[TS * DD];  // 32 KB
    int g  = threadIdx.x;
    int s0 = blockIdx.x * TS;

    for (int idx = g; idx < TS * DD; idx += GG) {
        int s2 = idx / DD;
        int kk = idx % DD;
        int sent = g_order[s0 + s2];
        shx[idx] = x[sent * DD + kk];
    }
    __syncthreads();

    ull a01[TS], a23[TS];
#pragma unroll
    for (int i = 0; i < TS; i++) { a01[i] = 0ull; a23[i] = 0ull; }

    const ulonglong2* W2 = reinterpret_cast<const ulonglong2*>(g_Wih0T);
    for (int k4 = 0; k4 < DD / 4; k4++) {
        ulonglong2 w = W2[k4 * GG + g];
#pragma unroll
        for (int s2 = 0; s2 < TS; s2++) {
            ulonglong2 xv = *reinterpret_cast<const ulonglong2*>(&shx[s2 * DD + 4 * k4]);
            fma2(a01[s2], w.x, xv.x);
            fma2(a23[s2], w.y, xv.y);
        }
    }
    float b = b_ih0[g];
#pragma unroll
    for (int s2 = 0; s2 < TS; s2++) {
        float2 p = unpk(a01[s2]), q = unpk(a23[s2]);
        g_xw0[(s0 + s2) * GG + g] = (p.x + p.y) + (q.x + q.y) + b;
    }
}

// ---------------- K3: 2-layer GRU, 4-CTA cluster, pipelined layers -----------
// R8 config: st.async to all 4 ranks (TX=1024, count=1), mapa pre-mapped,
// producer warps bar.arrive / gate warps bar.sync.
__global__ __launch_bounds__(GG, 1) __cluster_dims__(SUBS, 1, 1)
void k_gru(const float* __restrict__ W_hh0, const float* __restrict__ W_ih1,
           const float* __restrict__ W_hh1,
           const float* __restrict__ b_ih0, const float* __restrict__ b_hh0,
           const float* __restrict__ b_ih1, const float* __restrict__ b_hh1) {
    __shared__ __align__(16) float sh1[2][HH];
    __shared__ __align__(16) float sh2[2][HH];
    __shared__ float sp0[GG];
    __shared__ float sp1[GG];
    __shared__ __align__(8) unsigned long long mbar[2];

    int t   = threadIdx.x;
    int sub = blockIdx.x & (SUBS - 1);
    int c   = blockIdx.x / SUBS;

    // layer-0 role: 4 threads per row, 96 rows
    int q0 = t / 96;
    int i0 = t % 96;
    int g0 = i0 >> 5, e0 = i0 & 31;
    int R0 = 128 * g0 + 32 * sub + e0;

    // layer-1 role: 2 threads per row, 192 rows (96 Wih1 + 96 Whh1)
    int half = t / 192;
    int i1   = t % 192;
    int isW  = (i1 >= 96);
    int r1   = isW ? (i1 - 96) : i1;
    int g1 = r1 >> 5, e1 = r1 & 31;
    int R1 = 128 * g1 + 32 * sub + e1;

    // ---- register-resident weights (f32x2 pairs) ----
    ulonglong2 w0[8];
    const ulonglong2* p0 = reinterpret_cast<const ulonglong2*>(W_hh0 + R0 * HH + 32 * q0);
#pragma unroll
    for (int j = 0; j < 8; j++) w0[j] = p0[j];

    ulonglong2 w1[16];
    const float* Wsrc = isW ? W_hh1 : W_ih1;
    const ulonglong2* p1 = reinterpret_cast<const ulonglong2*>(Wsrc + R1 * HH + 64 * half);
#pragma unroll
    for (int j = 0; j < 16; j++) w1[j] = p1[j];

    // ---- biases: warp0 = layer0 gates, warp1 = layer1 gates ----
    float br_i = 0, bz_i = 0, bn_i = 0, br_h = 0, bz_h = 0, bn_h = 0;
    if (t < 32) {
        int e = 32 * sub + t;
        br_i = b_ih0[e]; bz_i = b_ih0[e + 128]; bn_i = b_ih0[e + 256];
        br_h = b_hh0[e]; bz_h = b_hh0[e + 128]; bn_h = b_hh0[e + 256];
    } else if (t < 64) {
        int e = 32 * sub + (t - 32);
        br_i = b_ih1[e]; bz_i = b_ih1[e + 128]; bn_i = b_ih1[e + 256];
        br_h = b_hh1[e]; bz_h = b_hh1[e + 128]; bn_h = b_hh1[e + 256];
    }

    if (t < HH) { sh1[0][t] = 0.f; sh1[1][t] = 0.f; sh2[0][t] = 0.f; sh2[1][t] = 0.f; }

    uint32_t mb[2];
    mb[0] = smem_u32(&mbar[0]); mb[1] = smem_u32(&mbar[1]);
    const uint32_t TX = 2 * HH * 4;  // 128 h1 + 128 h2 floats per phase
    if (t == 0) {
        asm volatile("mbarrier.init.shared.b64 [%0], 1;" :: "r"(mb[0]) : "memory");
        asm volatile("mbarrier.init.shared.b64 [%0], 1;" :: "r"(mb[1]) : "memory");
        rearm_bar(mb[0], TX); rearm_bar(mb[1], TX);
    }
    asm volatile("fence.proxy.async.shared::cta;" ::: "memory");
    __syncthreads();
    asm volatile("barrier.cluster.arrive.aligned;" ::: "memory");
    asm volatile("barrier.cluster.wait.aligned;" ::: "memory");

    int len   = g_len[c];
    int off   = g_off[c];
    int steps = len > 0 ? len : 1;

    uint32_t sh1a = smem_u32(&sh1[0][0]);
    uint32_t sh2a = smem_u32(&sh2[0][0]);

    // ---- pre-mapped remote bases ----
    uint32_t r_sh1[SUBS], r_sh2[SUBS], r_mb[SUBS];
#pragma unroll
    for (int p = 0; p < SUBS; p++) {
        r_sh1[p] = mapa_rank(sh1a, p);
        r_sh2[p] = mapa_rank(sh2a, p);
        r_mb[p]  = mapa_rank(mb[0], p);
    }

    float h2fin = 0.f;

    for (int s = 0; s <= steps; s++) {
        int rb1 = (s + 1) & 1;   // h1[s-1]
        int wb1 = s & 1;         // h1[s]
        int rb2 = s & 1;         // h2[s-2]
        int wb2 = (s + 1) & 1;   // h2[s-1]
        uint32_t mboff = (uint32_t)((s & 1) * 8);

        // prefetch input gates BEFORE the wait (overlaps L2 latency)
        float xwr = br_i, xwz = bz_i, xwn = bn_i;
        if (t < 32 && s < len) {
            const float* xp = g_xw0 + (off + s) * GG + 32 * sub + t;
            xwr = xp[0]; xwz = xp[128]; xwn = xp[256];
        }

        if (s > 0) {
            wait_bar(mb[(s - 1) & 1], (uint32_t)(((s - 1) >> 1) & 1));
            if (t == 0) rearm_bar(mb[(s - 1) & 1], TX);  // arm iter s+1
        }

        // ---- layer 0 matvec over h1[s-1] (f32x2) ----
        {
            ull a01 = 0ull, a23 = 0ull;
            const ulonglong2* hv = reinterpret_cast<const ulonglong2*>(&sh1[rb1][32 * q0]);
#pragma unroll
            for (int j = 0; j < 8; j++) {
                ulonglong2 h = hv[j];
                fma2(a01, w0[j].x, h.x);
                fma2(a23, w0[j].y, h.y);
            }
            float2 p = unpk(a01), q = unpk(a23);
            sp0[t] = (p.x + p.y) + (q.x + q.y);
        }
        // ---- layer 1 matvecs over h1[s-1] / h2[s-2] (f32x2) ----
        {
            const ulonglong2* hv = isW
                ? reinterpret_cast<const ulonglong2*>(&sh2[rb2][64 * half])
                : reinterpret_cast<const ulonglong2*>(&sh1[rb1][64 * half]);
            ull a01 = 0ull, a23 = 0ull;
#pragma unroll
            for (int j = 0; j < 16; j++) {
                ulonglong2 h = hv[j];
                fma2(a01, w1[j].x, h.x);
                fma2(a23, w1[j].y, h.y);
            }
            float2 p = unpk(a01), q = unpk(a23);
            sp1[t] = (p.x + p.y) + (q.x + q.y);
        }

        if (t >= 64) {
            // producers: post arrival, run ahead to next iteration's wait
            asm volatile("bar.arrive 1, 384;" ::: "memory");
            continue;
        }
        // consumers (gate warps): wait for all sp writes
        asm volatile("bar.sync 1, 384;" ::: "memory");

        if (t < 32) {
            float hr = sp0[t]      + sp0[96 + t]  + sp0[192 + t] + sp0[288 + t] + br_h;
            float hz = sp0[32 + t] + sp0[128 + t] + sp0[224 + t] + sp0[320 + t] + bz_h;
            float hn = sp0[64 + t] + sp0[160 + t] + sp0[256 + t] + sp0[352 + t] + bn_h;
            float rg = siga(xwr + hr);
            float zg = siga(xwz + hz);
            float ng = tanha(xwn + rg * hn);
            float h1o = sh1[rb1][32 * sub + t];
            float h1n = (1.f - zg) * ng + zg * h1o;
            uint32_t woff = (uint32_t)(wb1 * HH + 32 * sub + t) * 4u;
#pragma unroll
            for (int p = 0; p < SUBS; p++)
                st_async_pre(r_sh1[p] + woff, r_mb[p] + mboff, h1n);
        } else {
            int e = t - 32;
            float xr = sp1[e]       + sp1[192 + e] + br_i;
            float xz = sp1[32 + e]  + sp1[224 + e] + bz_i;
            float xn = sp1[64 + e]  + sp1[256 + e] + bn_i;
            float hr = sp1[96 + e]  + sp1[288 + e] + br_h;
            float hz = sp1[128 + e] + sp1[320 + e] + bz_h;
            float hn = sp1[160 + e] + sp1[352 + e] + bn_h;
            float rg = siga(xr + hr);
            float zg = siga(xz + hz);
            float ng = tanha(xn + rg * hn);
            float h2o = sh2[rb2][32 * sub + e];
            float h2n = (1.f - zg) * ng + zg * h2o;
            if (s == 0) h2n = 0.f;        // h2[-1] = initial state
            if (s == steps) h2fin = h2n;  // h2[steps-1] = final
            uint32_t woff = (uint32_t)(wb2 * HH + 32 * sub + e) * 4u;
#pragma unroll
            for (int p = 0; p < SUBS; p++)
                st_async_pre(r_sh2[p] + woff, r_mb[p] + mboff, h2n);
        }
    }

    // drain final exchange so no st.async is in flight at exit
    wait_bar(mb[steps & 1], (uint32_t)((steps >> 1) & 1));

    if (t >= 32 && t < 64) g_cemb[c * HH + 32 * sub + (t - 32)] = h2fin;

    asm volatile("barrier.cluster.arrive.aligned;" ::: "memory");
    asm volatile("barrier.cluster.wait.aligned;" ::: "memory");
}

// ---------------- K4: per-sentence scores (wn + cscore computed in-block) ----
__global__ __launch_bounds__(512) void k_score(const float* __restrict__ x,
                                               const int* __restrict__ labels,
                                               const float* __restrict__ lin_v,
                                               const float* __restrict__ lin_g,
                                               const float* __restrict__ lin_b) {
    __shared__ float swn[GG];
    __shared__ float red[16];
    __shared__ float scs[KK];
    int t = threadIdx.x;
    int warp = t >> 5, lane = t & 31;

    float v = (t < GG) ? lin_v[t] : 0.f;
    float sq = v * v;
    for (int o = 16; o > 0; o >>= 1) sq += __shfl_xor_sync(0xffffffffu, sq, o);
    if (lane == 0) red[warp] = sq;
    __syncthreads();
    if (t == 0) {
        float s = 0.f;
#pragma unroll
        for (int i = 0; i < 16; i++) s += red[i];
        red[0] = 1.f / sqrtf(s);
    }
    __syncthreads();
    if (t < GG) swn[t] = lin_g[0] * v * red[0];
    __syncthreads();

#pragma unroll
    for (int j = 0; j < 2; j++) {
        int c = warp * 2 + j;
        float s = 0.f;
#pragma unroll
        for (int q = 0; q < HH / 32; q++)
            s += g_cemb[c * HH + q * 32 + lane] * swn[DD + q * 32 + lane];
        for (int o = 16; o > 0; o >>= 1) s += __shfl_xor_sync(0xffffffffu, s, o);
        if (lane == 0) scs[c] = s;
    }
    __syncthreads();

    int i = blockIdx.x * 16 + warp;
    const float* xr = x + i * DD;
    float s = 0.f;
#pragma unroll
    for (int q = 0; q < DD / 32; q++)
        s += xr[q * 32 + lane] * swn[q * 32 + lane];
    for (int o = 16; o > 0; o >>= 1) s += __shfl_xor_sync(0xffffffffu, s, o);
    if (lane == 0)
        g_scores[i] = tanhf(s + scs[labels[i]] + lin_b[0]);
}

// ---------------- K5: segment sum + final combine ----------------------------
__global__ void k_tail(const int* __restrict__ labels, float* __restrict__ out) {
    __shared__ float s_sum[KK];
    __shared__ int   slab[NN];
    __shared__ float ssc[NN];
    int tid = threadIdx.x;
#pragma unroll
    for (int r = 0; r < NN / 1024; r++) {
        slab[r * 1024 + tid] = labels[r * 1024 + tid];
        ssc[r * 1024 + tid]  = g_scores[r * 1024 + tid];
    }
    __syncthreads();

    int c = tid >> 5, lane = tid & 31;
    float s = 0.f;
    for (int base = 0; base < NN; base += 32) {
        int lab = slab[base + lane];
        float v = ssc[base + lane];
        if (lab == c) s += v;
    }
    for (int o = 16; o > 0; o >>= 1) s += __shfl_xor_sync(0xffffffffu, s, o);
    if (lane == 0) s_sum[c] = s;
    __syncthreads();

#pragma unroll
    for (int r = 0; r < NN / 1024; r++) {
        int i = r * 1024 + tid;
        float sal = ssc[i] / s_sum[slab[i]];
        float p = fmaxf(0.5f, expf(-(float)(i + 1) * 0.0625f));  // 1/4096^(1/3)=1/16
        out[i] = 0.5f * sal + 0.5f * p;
    }
}

// ---------------- launch ------------------------------------------------------
extern "C" void kernel_launch(void* const* d_in, const int* in_sizes, int n_in,
                              void* d_out, int out_size) {
    const float* x     = (const float*)d_in[0];
    const int*   labels= (const int*)  d_in[1];
    const float* W_ih0 = (const float*)d_in[2];
    const float* W_hh0 = (const float*)d_in[3];
    const float* b_ih0 = (const float*)d_in[4];
    const float* b_hh0 = (const float*)d_in[5];
    const float* W_ih1 = (const float*)d_in[6];
    const float* W_hh1 = (const float*)d_in[7];
    const float* b_ih1 = (const float*)d_in[8];
    const float* b_hh1 = (const float*)d_in[9];
    const float* lin_v = (const float*)d_in[10];
    const float* lin_g = (const float*)d_in[11];
    const float* lin_b = (const float*)d_in[12];
    float* out = (float*)d_out;

    k_prep<<<25, 1024>>>(W_ih0, labels);
    k_xw0<<<NN / TS, GG>>>(x, b_ih0);
    k_gru<<<KK * SUBS, GG>>>(W_hh0, W_ih1, W_hh1, b_ih0, b_hh0, b_ih1, b_hh1);
    k_score<<<NN / 16, 512>>>(x, labels, lin_v, lin_g, lin_b);
    k_tail<<<1, 1024>>>(labels, out);
}

// round 14
// speedup vs baseline: 1.1162x; 1.0092x over previous
#include <cuda_runtime.h>
#include <math.h>
#include <stdint.h>

#define NN 4096
#define KK 32
#define DD 256
#define HH 128
#define GG 384   // 3*H
#define SUBS 4   // CTAs per cluster-sequence

typedef unsigned long long ull;

// ---------------- scratch (__device__ globals, no allocation) ----------------
__device__ int    g_order[NN];
__device__ int    g_len[KK];
__device__ int    g_off[KK];
__device__ float4 g_Wih0T[(DD/4)*GG];
__device__ float  g_xw0[NN*GG];
__device__ float  g_cemb[KK*HH];
__device__ float  g_scores[NN];

// ---------------- PTX helpers ------------------------------------------------
__device__ __forceinline__ uint32_t smem_u32(const void* p) {
    uint32_t a;
    asm("{ .reg .u64 t; cvta.to.shared.u64 t, %1; cvt.u32.u64 %0, t; }"
        : "=r"(a) : "l"(p));
    return a;
}
__device__ __forceinline__ uint32_t mapa_rank(uint32_t laddr, int rank) {
    uint32_t r;
    asm("mapa.shared::cluster.u32 %0, %1, %2;" : "=r"(r) : "r"(laddr), "r"(rank));
    return r;
}
__device__ __forceinline__ void st_async_pre(uint32_t raddr, uint32_t rmbar, float v) {
    uint32_t b = __float_as_uint(v);
    asm volatile("st.async.shared::cluster.mbarrier::complete_tx::bytes.b32 [%0], %1, [%2];"
                 :: "r"(raddr), "r"(b), "r"(rmbar) : "memory");
}
__device__ __forceinline__ void rearm_bar(uint32_t mbar, uint32_t txbytes) {
    asm volatile("mbarrier.arrive.expect_tx.shared::cta.b64 _, [%0], %1;"
                 :: "r"(mbar), "r"(txbytes) : "memory");
}
__device__ __forceinline__ void wait_bar(uint32_t mbar, uint32_t parity) {
    asm volatile(
        "{\n\t.reg .pred P;\n\t"
        "LW%=:\n\t"
        "mbarrier.try_wait.parity.acquire.cta.shared::cta.b64 P, [%0], %1;\n\t"
        "@!P bra LW%=;\n\t}"
        :: "r"(mbar), "r"(parity) : "memory");
}
__device__ __forceinline__ void fma2(ull& d, ull a, ull b) {
    asm("fma.rn.f32x2 %0, %1, %2, %0;" : "+l"(d) : "l"(a), "l"(b));
}
__device__ __forceinline__ float2 unpk(ull v) {
    float2 r;
    asm("mov.b64 {%0, %1}, %2;" : "=f"(r.x), "=f"(r.y) : "l"(v));
    return r;
}
__device__ __forceinline__ float tanha(float x) {
    float y;
    asm("tanh.approx.f32 %0, %1;" : "=f"(y) : "f"(x));
    return y;
}
__device__ __forceinline__ float siga(float x) {
    return fmaf(0.5f, tanha(0.5f * x), 0.5f);
}

// ---------------- K0: fused transpose (blocks 0..23) + order (block 24) -----
__global__ __launch_bounds__(1024) void k_prep(const float* __restrict__ W_ih0,
                                               const int* __restrict__ labels) {
    if (blockIdx.x < 24) {
        int idx = blockIdx.x * 1024 + threadIdx.x;
        int k4 = idx & 63;
        int g  = idx >> 6;
        float4 v = *reinterpret_cast<const float4*>(W_ih0 + g * DD + 4 * k4);
        g_Wih0T[k4 * GG + g] = v;
        return;
    }
    __shared__ int slab[NN];
    __shared__ int s_len[KK];
    __shared__ int s_off[KK];
    int tid = threadIdx.x;
    int c    = tid >> 5;
    int lane = tid & 31;

#pragma unroll
    for (int r = 0; r < NN / 1024; r++)
        slab[r * 1024 + tid] = labels[r * 1024 + tid];
    __syncthreads();

    int count = 0;
    for (int base = 0; base < NN; base += 32) {
        int lab = slab[base + lane];
        unsigned m = __ballot_sync(0xffffffffu, lab == c);
        count += __popc(m);
    }
    if (lane == 0) s_len[c] = count;
    __syncthreads();

    if (c == 0) {
        int len = s_len[lane];
        int off = 0;
        for (int j = 0; j < KK; j++) {
            int lj = __shfl_sync(0xffffffffu, len, j);
            if (j < lane) off += lj;
        }
        s_off[lane] = off;
        g_len[lane] = len;
        g_off[lane] = off;
    }
    __syncthreads();

    int off = s_off[c];
    int cnt = 0;
    for (int base = 0; base < NN; base += 32) {
        int lab = slab[base + lane];
        unsigned m = __ballot_sync(0xffffffffu, lab == c);
        if (lab == c) {
            int p = cnt + __popc(m & ((1u << lane) - 1u));
            g_order[off + p] = base + lane;
        }
        cnt += __popc(m);
    }
}

// ---------------- K2: xw0 = X_gathered @ W_ih0^T + b_ih0 (f32x2, TS=16) -----
#define TS 16
__global__ __launch_bounds__(GG) void k_xw0(const float* __restrict__ x,
                                            const float* __restrict__ b_ih0) {
    __shared__ __align__(16) float shx[TS * DD];
    int g  = threadIdx.x;
    int s0 = blockIdx.x * TS;

    for (int idx = g; idx < TS * DD; idx += GG) {
        int s2 = idx / DD;
        int kk = idx % DD;
        int sent = g_order[s0 + s2];
        shx[idx] = x[sent * DD + kk];
    }
    __syncthreads();

    ull a01[TS], a23[TS];
#pragma unroll
    for (int i = 0; i < TS; i++) { a01[i] = 0ull; a23[i] = 0ull; }

    const ulonglong2* W2 = reinterpret_cast<const ulonglong2*>(g_Wih0T);
    for (int k4 = 0; k4 < DD / 4; k4++) {
        ulonglong2 w = W2[k4 * GG + g];
#pragma unroll
        for (int s2 = 0; s2 < TS; s2++) {
            ulonglong2 xv = *reinterpret_cast<const ulonglong2*>(&shx[s2 * DD + 4 * k4]);
            fma2(a01[s2], w.x, xv.x);
            fma2(a23[s2], w.y, xv.y);
        }
    }
    float b = b_ih0[g];
#pragma unroll
    for (int s2 = 0; s2 < TS; s2++) {
        float2 p = unpk(a01[s2]), q = unpk(a23[s2]);
        g_xw0[(s0 + s2) * GG + g] = (p.x + p.y) + (q.x + q.y) + b;
    }
}

// ---------------- K3: 2-layer GRU, 4-CTA cluster, pipelined layers -----------
// R8 config: st.async to all 4 ranks (TX=1024, count=1), mapa pre-mapped,
// producer warps bar.arrive / gate warps bar.sync.
__global__ __launch_bounds__(GG, 1) __cluster_dims__(SUBS, 1, 1)
void k_gru(const float* __restrict__ W_hh0, const float* __restrict__ W_ih1,
           const float* __restrict__ W_hh1,
           const float* __restrict__ b_ih0, const float* __restrict__ b_hh0,
           const float* __restrict__ b_ih1, const float* __restrict__ b_hh1) {
    __shared__ __align__(16) float sh1[2][HH];
    __shared__ __align__(16) float sh2[2][HH];
    __shared__ float sp0[GG];
    __shared__ float sp1[GG];
    __shared__ __align__(8) unsigned long long mbar[2];

    int t   = threadIdx.x;
    int sub = blockIdx.x & (SUBS - 1);
    int c   = blockIdx.x / SUBS;

    // layer-0 role: 4 threads per row, 96 rows
    int q0 = t / 96;
    int i0 = t % 96;
    int g0 = i0 >> 5, e0 = i0 & 31;
    int R0 = 128 * g0 + 32 * sub + e0;

    // layer-1 role: 2 threads per row, 192 rows (96 Wih1 + 96 Whh1)
    int half = t / 192;
    int i1   = t % 192;
    int isW  = (i1 >= 96);
    int r1   = isW ? (i1 - 96) : i1;
    int g1 = r1 >> 5, e1 = r1 & 31;
    int R1 = 128 * g1 + 32 * sub + e1;

    // ---- register-resident weights (f32x2 pairs) ----
    ulonglong2 w0[8];
    const ulonglong2* p0 = reinterpret_cast<const ulonglong2*>(W_hh0 + R0 * HH + 32 * q0);
#pragma unroll
    for (int j = 0; j < 8; j++) w0[j] = p0[j];

    ulonglong2 w1[16];
    const float* Wsrc = isW ? W_hh1 : W_ih1;
    const ulonglong2* p1 = reinterpret_cast<const ulonglong2*>(Wsrc + R1 * HH + 64 * half);
#pragma unroll
    for (int j = 0; j < 16; j++) w1[j] = p1[j];

    // ---- biases: warp0 = layer0 gates, warp1 = layer1 gates ----
    float br_i = 0, bz_i = 0, bn_i = 0, br_h = 0, bz_h = 0, bn_h = 0;
    if (t < 32) {
        int e = 32 * sub + t;
        br_i = b_ih0[e]; bz_i = b_ih0[e + 128]; bn_i = b_ih0[e + 256];
        br_h = b_hh0[e]; bz_h = b_hh0[e + 128]; bn_h = b_hh0[e + 256];
    } else if (t < 64) {
        int e = 32 * sub + (t - 32);
        br_i = b_ih1[e]; bz_i = b_ih1[e + 128]; bn_i = b_ih1[e + 256];
        br_h = b_hh1[e]; bz_h = b_hh1[e + 128]; bn_h = b_hh1[e + 256];
    }

    if (t < HH) { sh1[0][t] = 0.f; sh1[1][t] = 0.f; sh2[0][t] = 0.f; sh2[1][t] = 0.f; }

    uint32_t mb[2];
    mb[0] = smem_u32(&mbar[0]); mb[1] = smem_u32(&mbar[1]);
    const uint32_t TX = 2 * HH * 4;  // 128 h1 + 128 h2 floats per phase
    if (t == 0) {
        asm volatile("mbarrier.init.shared.b64 [%0], 1;" :: "r"(mb[0]) : "memory");
        asm volatile("mbarrier.init.shared.b64 [%0], 1;" :: "r"(mb[1]) : "memory");
        rearm_bar(mb[0], TX); rearm_bar(mb[1], TX);
    }
    asm volatile("fence.proxy.async.shared::cta;" ::: "memory");
    __syncthreads();
    asm volatile("barrier.cluster.arrive.aligned;" ::: "memory");
    asm volatile("barrier.cluster.wait.aligned;" ::: "memory");

    int len   = g_len[c];
    int off   = g_off[c];
    int steps = len > 0 ? len : 1;

    uint32_t sh1a = smem_u32(&sh1[0][0]);
    uint32_t sh2a = smem_u32(&sh2[0][0]);

    // ---- pre-mapped remote bases ----
    uint32_t r_sh1[SUBS], r_sh2[SUBS], r_mb[SUBS];
#pragma unroll
    for (int p = 0; p < SUBS; p++) {
        r_sh1[p] = mapa_rank(sh1a, p);
        r_sh2[p] = mapa_rank(sh2a, p);
        r_mb[p]  = mapa_rank(mb[0], p);
    }

    float h2fin = 0.f;

    for (int s = 0; s <= steps; s++) {
        int rb1 = (s + 1) & 1;   // h1[s-1]
        int wb1 = s & 1;         // h1[s]
        int rb2 = s & 1;         // h2[s-2]
        int wb2 = (s + 1) & 1;   // h2[s-1]
        uint32_t mboff = (uint32_t)((s & 1) * 8);

        // prefetch input gates BEFORE the wait (overlaps L2 latency)
        float xwr = br_i, xwz = bz_i, xwn = bn_i;
        if (t < 32 && s < len) {
            const float* xp = g_xw0 + (off + s) * GG + 32 * sub + t;
            xwr = xp[0]; xwz = xp[128]; xwn = xp[256];
        }

        if (s > 0) {
            wait_bar(mb[(s - 1) & 1], (uint32_t)(((s - 1) >> 1) & 1));
            if (t == 0) rearm_bar(mb[(s - 1) & 1], TX);  // arm iter s+1
        }

        // ---- layer 0 matvec over h1[s-1] (f32x2) ----
        {
            ull a01 = 0ull, a23 = 0ull;
            const ulonglong2* hv = reinterpret_cast<const ulonglong2*>(&sh1[rb1][32 * q0]);
#pragma unroll
            for (int j = 0; j < 8; j++) {
                ulonglong2 h = hv[j];
                fma2(a01, w0[j].x, h.x);
                fma2(a23, w0[j].y, h.y);
            }
            float2 p = unpk(a01), q = unpk(a23);
            sp0[t] = (p.x + p.y) + (q.x + q.y);
        }
        // ---- layer 1 matvecs over h1[s-1] / h2[s-2] (f32x2) ----
        {
            const ulonglong2* hv = isW
                ? reinterpret_cast<const ulonglong2*>(&sh2[rb2][64 * half])
                : reinterpret_cast<const ulonglong2*>(&sh1[rb1][64 * half]);
            ull a01 = 0ull, a23 = 0ull;
#pragma unroll
            for (int j = 0; j < 16; j++) {
                ulonglong2 h = hv[j];
                fma2(a01, w1[j].x, h.x);
                fma2(a23, w1[j].y, h.y);
            }
            float2 p = unpk(a01), q = unpk(a23);
            sp1[t] = (p.x + p.y) + (q.x + q.y);
        }

        if (t >= 64) {
            // producers: post arrival, run ahead to next iteration's wait
            asm volatile("bar.arrive 1, 384;" ::: "memory");
            continue;
        }
        // consumers (gate warps): wait for all sp writes
        asm volatile("bar.sync 1, 384;" ::: "memory");

        if (t < 32) {
            float hr = sp0[t]      + sp0[96 + t]  + sp0[192 + t] + sp0[288 + t] + br_h;
            float hz = sp0[32 + t] + sp0[128 + t] + sp0[224 + t] + sp0[320 + t] + bz_h;
            float hn = sp0[64 + t] + sp0[160 + t] + sp0[256 + t] + sp0[352 + t] + bn_h;
            float rg = siga(xwr + hr);
            float zg = siga(xwz + hz);
            float ng = tanha(xwn + rg * hn);
            float h1o = sh1[rb1][32 * sub + t];
            float h1n = (1.f - zg) * ng + zg * h1o;
            uint32_t woff = (uint32_t)(wb1 * HH + 32 * sub + t) * 4u;
#pragma unroll
            for (int p = 0; p < SUBS; p++)
                st_async_pre(r_sh1[p] + woff, r_mb[p] + mboff, h1n);
        } else {
            int e = t - 32;
            float xr = sp1[e]       + sp1[192 + e] + br_i;
            float xz = sp1[32 + e]  + sp1[224 + e] + bz_i;
            float xn = sp1[64 + e]  + sp1[256 + e] + bn_i;
            float hr = sp1[96 + e]  + sp1[288 + e] + br_h;
            float hz = sp1[128 + e] + sp1[320 + e] + bz_h;
            float hn = sp1[160 + e] + sp1[352 + e] + bn_h;
            float rg = siga(xr + hr);
            float zg = siga(xz + hz);
            float ng = tanha(xn + rg * hn);
            float h2o = sh2[rb2][32 * sub + e];
            float h2n = (1.f - zg) * ng + zg * h2o;
            if (s == 0) h2n = 0.f;        // h2[-1] = initial state
            if (s == steps) h2fin = h2n;  // h2[steps-1] = final
            uint32_t woff = (uint32_t)(wb2 * HH + 32 * sub + e) * 4u;
#pragma unroll
            for (int p = 0; p < SUBS; p++)
                st_async_pre(r_sh2[p] + woff, r_mb[p] + mboff, h2n);
        }
    }

    // drain final exchange so no st.async is in flight at exit
    wait_bar(mb[steps & 1], (uint32_t)((steps >> 1) & 1));

    if (t >= 32 && t < 64) g_cemb[c * HH + 32 * sub + (t - 32)] = h2fin;

    asm volatile("barrier.cluster.arrive.aligned;" ::: "memory");
    asm volatile("barrier.cluster.wait.aligned;" ::: "memory");
}

// ---------------- K4: per-sentence scores (float4 loads) ---------------------
__global__ __launch_bounds__(512) void k_score(const float* __restrict__ x,
                                               const int* __restrict__ labels,
                                               const float* __restrict__ lin_v,
                                               const float* __restrict__ lin_g,
                                               const float* __restrict__ lin_b) {
    __shared__ __align__(16) float swn[GG];
    __shared__ float red[16];
    __shared__ float scs[KK];
    int t = threadIdx.x;
    int warp = t >> 5, lane = t & 31;

    float v = (t < GG) ? lin_v[t] : 0.f;
    float sq = v * v;
    for (int o = 16; o > 0; o >>= 1) sq += __shfl_xor_sync(0xffffffffu, sq, o);
    if (lane == 0) red[warp] = sq;
    __syncthreads();
    if (t == 0) {
        float s = 0.f;
#pragma unroll
        for (int i = 0; i < 16; i++) s += red[i];
        red[0] = 1.f / sqrtf(s);
    }
    __syncthreads();
    if (t < GG) swn[t] = lin_g[0] * v * red[0];
    __syncthreads();

#pragma unroll
    for (int j = 0; j < 2; j++) {
        int c = warp * 2 + j;
        float s = 0.f;
#pragma unroll
        for (int q = 0; q < HH / 32; q++)
            s += g_cemb[c * HH + q * 32 + lane] * swn[DD + q * 32 + lane];
        for (int o = 16; o > 0; o >>= 1) s += __shfl_xor_sync(0xffffffffu, s, o);
        if (lane == 0) scs[c] = s;
    }
    __syncthreads();

    // ---- sentence score: one warp per sentence, float4 loads ----
    int i = blockIdx.x * 16 + warp;
    const float4* xr4 = reinterpret_cast<const float4*>(x + i * DD);
    const float4* wn4 = reinterpret_cast<const float4*>(swn);
    float4 xa = xr4[lane * 2], xb = xr4[lane * 2 + 1];
    float4 wa = wn4[lane * 2], wb = wn4[lane * 2 + 1];
    float s = (xa.x * wa.x + xa.y * wa.y) + (xa.z * wa.z + xa.w * wa.w)
            + (xb.x * wb.x + xb.y * wb.y) + (xb.z * wb.z + xb.w * wb.w);
    for (int o = 16; o > 0; o >>= 1) s += __shfl_xor_sync(0xffffffffu, s, o);
    if (lane == 0)
        g_scores[i] = tanhf(s + scs[labels[i]] + lin_b[0]);
}

// ---------------- K5: segment sum + final combine ----------------------------
__global__ void k_tail(const int* __restrict__ labels, float* __restrict__ out) {
    __shared__ float s_sum[KK];
    __shared__ int   slab[NN];
    __shared__ float ssc[NN];
    int tid = threadIdx.x;
#pragma unroll
    for (int r = 0; r < NN / 1024; r++) {
        slab[r * 1024 + tid] = labels[r * 1024 + tid];
        ssc[r * 1024 + tid]  = g_scores[r * 1024 + tid];
    }
    __syncthreads();

    int c = tid >> 5, lane = tid & 31;
    float s = 0.f;
    for (int base = 0; base < NN; base += 32) {
        int lab = slab[base + lane];
        float v = ssc[base + lane];
        if (lab == c) s += v;
    }
    for (int o = 16; o > 0; o >>= 1) s += __shfl_xor_sync(0xffffffffu, s, o);
    if (lane == 0) s_sum[c] = s;
    __syncthreads();

#pragma unroll
    for (int r = 0; r < NN / 1024; r++) {
        int i = r * 1024 + tid;
        float sal = ssc[i] / s_sum[slab[i]];
        float p = fmaxf(0.5f, expf(-(float)(i + 1) * 0.0625f));  // 1/4096^(1/3)=1/16
        out[i] = 0.5f * sal + 0.5f * p;
    }
}

// ---------------- launch ------------------------------------------------------
extern "C" void kernel_launch(void* const* d_in, const int* in_sizes, int n_in,
                              void* d_out, int out_size) {
    const float* x     = (const float*)d_in[0];
    const int*   labels= (const int*)  d_in[1];
    const float* W_ih0 = (const float*)d_in[2];
    const float* W_hh0 = (const float*)d_in[3];
    const float* b_ih0 = (const float*)d_in[4];
    const float* b_hh0 = (const float*)d_in[5];
    const float* W_ih1 = (const float*)d_in[6];
    const float* W_hh1 = (const float*)d_in[7];
    const float* b_ih1 = (const float*)d_in[8];
    const float* b_hh1 = (const float*)d_in[9];
    const float* lin_v = (const float*)d_in[10];
    const float* lin_g = (const float*)d_in[11];
    const float* lin_b = (const float*)d_in[12];
    float* out = (float*)d_out;

    k_prep<<<25, 1024>>>(W_ih0, labels);
    k_xw0<<<NN / TS, GG>>>(x, b_ih0);
    k_gru<<<KK * SUBS, GG>>>(W_hh0, W_ih1, W_hh1, b_ih0, b_hh0, b_ih1, b_hh1);
    k_score<<<NN / 16, 512>>>(x, labels, lin_v, lin_g, lin_b);
    k_tail<<<1, 1024>>>(labels, out);
}

// round 15
// speedup vs baseline: 1.1173x; 1.0010x over previous
#include <cuda_runtime.h>
#include <math.h>
#include <stdint.h>

#define NN 4096
#define KK 32
#define DD 256
#define HH 128
#define GG 384   // 3*H
#define SUBS 4   // CTAs per cluster-sequence

typedef unsigned long long ull;

// ---------------- scratch (__device__ globals, no allocation) ----------------
__device__ int    g_order[NN];
__device__ int    g_len[KK];
__device__ int    g_off[KK];
__device__ float4 g_Wih0T[(DD/4)*GG];
__device__ float  g_xw0[NN*GG];
__device__ float  g_cemb[KK*HH];
__device__ float  g_scores[NN];

// ---------------- PTX helpers ------------------------------------------------
__device__ __forceinline__ uint32_t smem_u32(const void* p) {
    uint32_t a;
    asm("{ .reg .u64 t; cvta.to.shared.u64 t, %1; cvt.u32.u64 %0, t; }"
        : "=r"(a) : "l"(p));
    return a;
}
__device__ __forceinline__ uint32_t mapa_rank(uint32_t laddr, int rank) {
    uint32_t r;
    asm("mapa.shared::cluster.u32 %0, %1, %2;" : "=r"(r) : "r"(laddr), "r"(rank));
    return r;
}
__device__ __forceinline__ void st_async_pre(uint32_t raddr, uint32_t rmbar, float v) {
    uint32_t b = __float_as_uint(v);
    asm volatile("st.async.shared::cluster.mbarrier::complete_tx::bytes.b32 [%0], %1, [%2];"
                 :: "r"(raddr), "r"(b), "r"(rmbar) : "memory");
}
__device__ __forceinline__ void rearm_bar(uint32_t mbar, uint32_t txbytes) {
    asm volatile("mbarrier.arrive.expect_tx.shared::cta.b64 _, [%0], %1;"
                 :: "r"(mbar), "r"(txbytes) : "memory");
}
__device__ __forceinline__ void wait_bar(uint32_t mbar, uint32_t parity) {
    asm volatile(
        "{\n\t.reg .pred P;\n\t"
        "LW%=:\n\t"
        "mbarrier.try_wait.parity.acquire.cta.shared::cta.b64 P, [%0], %1;\n\t"
        "@!P bra LW%=;\n\t}"
        :: "r"(mbar), "r"(parity) : "memory");
}
__device__ __forceinline__ void fma2(ull& d, ull a, ull b) {
    asm("fma.rn.f32x2 %0, %1, %2, %0;" : "+l"(d) : "l"(a), "l"(b));
}
__device__ __forceinline__ float2 unpk(ull v) {
    float2 r;
    asm("mov.b64 {%0, %1}, %2;" : "=f"(r.x), "=f"(r.y) : "l"(v));
    return r;
}
__device__ __forceinline__ float tanha(float x) {
    float y;
    asm("tanh.approx.f32 %0, %1;" : "=f"(y) : "f"(x));
    return y;
}
__device__ __forceinline__ float siga(float x) {
    return fmaf(0.5f, tanha(0.5f * x), 0.5f);
}

// ---------------- K0: fused transpose (blocks 0..23) + order (block 24) -----
__global__ __launch_bounds__(1024) void k_prep(const float* __restrict__ W_ih0,
                                               const int* __restrict__ labels) {
    if (blockIdx.x < 24) {
        int idx = blockIdx.x * 1024 + threadIdx.x;
        int k4 = idx & 63;
        int g  = idx >> 6;
        float4 v = *reinterpret_cast<const float4*>(W_ih0 + g * DD + 4 * k4);
        g_Wih0T[k4 * GG + g] = v;
        return;
    }
    __shared__ int slab[NN];
    __shared__ int s_len[KK];
    __shared__ int s_off[KK];
    int tid = threadIdx.x;
    int c    = tid >> 5;
    int lane = tid & 31;

#pragma unroll
    for (int r = 0; r < NN / 1024; r++)
        slab[r * 1024 + tid] = labels[r * 1024 + tid];
    __syncthreads();

    int count = 0;
    for (int base = 0; base < NN; base += 32) {
        int lab = slab[base + lane];
        unsigned m = __ballot_sync(0xffffffffu, lab == c);
        count += __popc(m);
    }
    if (lane == 0) s_len[c] = count;
    __syncthreads();

    if (c == 0) {
        int len = s_len[lane];
        int off = 0;
        for (int j = 0; j < KK; j++) {
            int lj = __shfl_sync(0xffffffffu, len, j);
            if (j < lane) off += lj;
        }
        s_off[lane] = off;
        g_len[lane] = len;
        g_off[lane] = off;
    }
    __syncthreads();

    int off = s_off[c];
    int cnt = 0;
    for (int base = 0; base < NN; base += 32) {
        int lab = slab[base + lane];
        unsigned m = __ballot_sync(0xffffffffu, lab == c);
        if (lab == c) {
            int p = cnt + __popc(m & ((1u << lane) - 1u));
            g_order[off + p] = base + lane;
        }
        cnt += __popc(m);
    }
}

// ---------------- K2: xw0 = X_gathered @ W_ih0^T + b_ih0 (f32x2, TS=16) -----
#define TS 16
__global__ __launch_bounds__(GG) void k_xw0(const float* __restrict__ x,
                                            const float* __restrict__ b_ih0) {
    __shared__ __align__(16) float shx[TS * DD];
    int g  = threadIdx.x;
    int s0 = blockIdx.x * TS;

    for (int idx = g; idx < TS * DD; idx += GG) {
        int s2 = idx / DD;
        int kk = idx % DD;
        int sent = g_order[s0 + s2];
        shx[idx] = x[sent * DD + kk];
    }
    __syncthreads();

    ull a01[TS], a23[TS];
#pragma unroll
    for (int i = 0; i < TS; i++) { a01[i] = 0ull; a23[i] = 0ull; }

    const ulonglong2* W2 = reinterpret_cast<const ulonglong2*>(g_Wih0T);
    for (int k4 = 0; k4 < DD / 4; k4++) {
        ulonglong2 w = W2[k4 * GG + g];
#pragma unroll
        for (int s2 = 0; s2 < TS; s2++) {
            ulonglong2 xv = *reinterpret_cast<const ulonglong2*>(&shx[s2 * DD + 4 * k4]);
            fma2(a01[s2], w.x, xv.x);
            fma2(a23[s2], w.y, xv.y);
        }
    }
    float b = b_ih0[g];
#pragma unroll
    for (int s2 = 0; s2 < TS; s2++) {
        float2 p = unpk(a01[s2]), q = unpk(a23[s2]);
        g_xw0[(s0 + s2) * GG + g] = (p.x + p.y) + (q.x + q.y) + b;
    }
}

// ---------------- K3: 2-layer GRU, 4-CTA cluster, pipelined layers -----------
// R8 config: st.async to all 4 ranks (TX=1024, count=1), mapa pre-mapped,
// producer warps bar.arrive / gate warps bar.sync. Rearm done by producer
// thread t==383 (off the gate critical path).
__global__ __launch_bounds__(GG, 1) __cluster_dims__(SUBS, 1, 1)
void k_gru(const float* __restrict__ W_hh0, const float* __restrict__ W_ih1,
           const float* __restrict__ W_hh1,
           const float* __restrict__ b_ih0, const float* __restrict__ b_hh0,
           const float* __restrict__ b_ih1, const float* __restrict__ b_hh1) {
    __shared__ __align__(16) float sh1[2][HH];
    __shared__ __align__(16) float sh2[2][HH];
    __shared__ float sp0[GG];
    __shared__ float sp1[GG];
    __shared__ __align__(8) unsigned long long mbar[2];

    int t   = threadIdx.x;
    int sub = blockIdx.x & (SUBS - 1);
    int c   = blockIdx.x / SUBS;

    // layer-0 role: 4 threads per row, 96 rows
    int q0 = t / 96;
    int i0 = t % 96;
    int g0 = i0 >> 5, e0 = i0 & 31;
    int R0 = 128 * g0 + 32 * sub + e0;

    // layer-1 role: 2 threads per row, 192 rows (96 Wih1 + 96 Whh1)
    int half = t / 192;
    int i1   = t % 192;
    int isW  = (i1 >= 96);
    int r1   = isW ? (i1 - 96) : i1;
    int g1 = r1 >> 5, e1 = r1 & 31;
    int R1 = 128 * g1 + 32 * sub + e1;

    // ---- register-resident weights (f32x2 pairs) ----
    ulonglong2 w0[8];
    const ulonglong2* p0 = reinterpret_cast<const ulonglong2*>(W_hh0 + R0 * HH + 32 * q0);
#pragma unroll
    for (int j = 0; j < 8; j++) w0[j] = p0[j];

    ulonglong2 w1[16];
    const float* Wsrc = isW ? W_hh1 : W_ih1;
    const ulonglong2* p1 = reinterpret_cast<const ulonglong2*>(Wsrc + R1 * HH + 64 * half);
#pragma unroll
    for (int j = 0; j < 16; j++) w1[j] = p1[j];

    // ---- biases: warp0 = layer0 gates, warp1 = layer1 gates ----
    float br_i = 0, bz_i = 0, bn_i = 0, br_h = 0, bz_h = 0, bn_h = 0;
    if (t < 32) {
        int e = 32 * sub + t;
        br_i = b_ih0[e]; bz_i = b_ih0[e + 128]; bn_i = b_ih0[e + 256];
        br_h = b_hh0[e]; bz_h = b_hh0[e + 128]; bn_h = b_hh0[e + 256];
    } else if (t < 64) {
        int e = 32 * sub + (t - 32);
        br_i = b_ih1[e]; bz_i = b_ih1[e + 128]; bn_i = b_ih1[e + 256];
        br_h = b_hh1[e]; bz_h = b_hh1[e + 128]; bn_h = b_hh1[e + 256];
    }

    if (t < HH) { sh1[0][t] = 0.f; sh1[1][t] = 0.f; sh2[0][t] = 0.f; sh2[1][t] = 0.f; }

    uint32_t mb[2];
    mb[0] = smem_u32(&mbar[0]); mb[1] = smem_u32(&mbar[1]);
    const uint32_t TX = 2 * HH * 4;  // 128 h1 + 128 h2 floats per phase
    if (t == 0) {
        asm volatile("mbarrier.init.shared.b64 [%0], 1;" :: "r"(mb[0]) : "memory");
        asm volatile("mbarrier.init.shared.b64 [%0], 1;" :: "r"(mb[1]) : "memory");
        rearm_bar(mb[0], TX); rearm_bar(mb[1], TX);
    }
    asm volatile("fence.proxy.async.shared::cta;" ::: "memory");
    __syncthreads();
    asm volatile("barrier.cluster.arrive.aligned;" ::: "memory");
    asm volatile("barrier.cluster.wait.aligned;" ::: "memory");

    int len   = g_len[c];
    int off   = g_off[c];
    int steps = len > 0 ? len : 1;

    uint32_t sh1a = smem_u32(&sh1[0][0]);
    uint32_t sh2a = smem_u32(&sh2[0][0]);

    // ---- pre-mapped remote bases ----
    uint32_t r_sh1[SUBS], r_sh2[SUBS], r_mb[SUBS];
#pragma unroll
    for (int p = 0; p < SUBS; p++) {
        r_sh1[p] = mapa_rank(sh1a, p);
        r_sh2[p] = mapa_rank(sh2a, p);
        r_mb[p]  = mapa_rank(mb[0], p);
    }

    float h2fin = 0.f;

    for (int s = 0; s <= steps; s++) {
        int rb1 = (s + 1) & 1;   // h1[s-1]
        int wb1 = s & 1;         // h1[s]
        int rb2 = s & 1;         // h2[s-2]
        int wb2 = (s + 1) & 1;   // h2[s-1]
        uint32_t mboff = (uint32_t)((s & 1) * 8);

        // prefetch input gates BEFORE the wait (overlaps L2 latency)
        float xwr = br_i, xwz = bz_i, xwn = bn_i;
        if (t < 32 && s < len) {
            const float* xp = g_xw0 + (off + s) * GG + 32 * sub + t;
            xwr = xp[0]; xwz = xp[128]; xwn = xp[256];
        }

        if (s > 0) {
            wait_bar(mb[(s - 1) & 1], (uint32_t)(((s - 1) >> 1) & 1));
            if (t == 383) rearm_bar(mb[(s - 1) & 1], TX);  // arm iter s+1 (producer thread)
        }

        // ---- layer 0 matvec over h1[s-1] (f32x2) ----
        {
            ull a01 = 0ull, a23 = 0ull;
            const ulonglong2* hv = reinterpret_cast<const ulonglong2*>(&sh1[rb1][32 * q0]);
#pragma unroll
            for (int j = 0; j < 8; j++) {
                ulonglong2 h = hv[j];
                fma2(a01, w0[j].x, h.x);
                fma2(a23, w0[j].y, h.y);
            }
            float2 p = unpk(a01), q = unpk(a23);
            sp0[t] = (p.x + p.y) + (q.x + q.y);
        }
        // ---- layer 1 matvecs over h1[s-1] / h2[s-2] (f32x2) ----
        {
            const ulonglong2* hv = isW
                ? reinterpret_cast<const ulonglong2*>(&sh2[rb2][64 * half])
                : reinterpret_cast<const ulonglong2*>(&sh1[rb1][64 * half]);
            ull a01 = 0ull, a23 = 0ull;
#pragma unroll
            for (int j = 0; j < 16; j++) {
                ulonglong2 h = hv[j];
                fma2(a01, w1[j].x, h.x);
                fma2(a23, w1[j].y, h.y);
            }
            float2 p = unpk(a01), q = unpk(a23);
            sp1[t] = (p.x + p.y) + (q.x + q.y);
        }

        if (t >= 64) {
            // producers: post arrival, run ahead to next iteration's wait
            asm volatile("bar.arrive 1, 384;" ::: "memory");
            continue;
        }
        // consumers (gate warps): wait for all sp writes
        asm volatile("bar.sync 1, 384;" ::: "memory");

        if (t < 32) {
            float hr = sp0[t]      + sp0[96 + t]  + sp0[192 + t] + sp0[288 + t] + br_h;
            float hz = sp0[32 + t] + sp0[128 + t] + sp0[224 + t] + sp0[320 + t] + bz_h;
            float hn = sp0[64 + t] + sp0[160 + t] + sp0[256 + t] + sp0[352 + t] + bn_h;
            float rg = siga(xwr + hr);
            float zg = siga(xwz + hz);
            float ng = tanha(xwn + rg * hn);
            float h1o = sh1[rb1][32 * sub + t];
            float h1n = (1.f - zg) * ng + zg * h1o;
            uint32_t woff = (uint32_t)(wb1 * HH + 32 * sub + t) * 4u;
#pragma unroll
            for (int p = 0; p < SUBS; p++)
                st_async_pre(r_sh1[p] + woff, r_mb[p] + mboff, h1n);
        } else {
            int e = t - 32;
            float xr = sp1[e]       + sp1[192 + e] + br_i;
            float xz = sp1[32 + e]  + sp1[224 + e] + bz_i;
            float xn = sp1[64 + e]  + sp1[256 + e] + bn_i;
            float hr = sp1[96 + e]  + sp1[288 + e] + br_h;
            float hz = sp1[128 + e] + sp1[320 + e] + bz_h;
            float hn = sp1[160 + e] + sp1[352 + e] + bn_h;
            float rg = siga(xr + hr);
            float zg = siga(xz + hz);
            float ng = tanha(xn + rg * hn);
            float h2o = sh2[rb2][32 * sub + e];
            float h2n = (1.f - zg) * ng + zg * h2o;
            if (s == 0) h2n = 0.f;        // h2[-1] = initial state
            if (s == steps) h2fin = h2n;  // h2[steps-1] = final
            uint32_t woff = (uint32_t)(wb2 * HH + 32 * sub + e) * 4u;
#pragma unroll
            for (int p = 0; p < SUBS; p++)
                st_async_pre(r_sh2[p] + woff, r_mb[p] + mboff, h2n);
        }
    }

    // drain final exchange so no st.async is in flight at exit
    wait_bar(mb[steps & 1], (uint32_t)((steps >> 1) & 1));

    if (t >= 32 && t < 64) g_cemb[c * HH + 32 * sub + (t - 32)] = h2fin;

    asm volatile("barrier.cluster.arrive.aligned;" ::: "memory");
    asm volatile("barrier.cluster.wait.aligned;" ::: "memory");
}

// ---------------- K4: per-sentence scores (wn + cscore computed in-block) ----
__global__ __launch_bounds__(512) void k_score(const float* __restrict__ x,
                                               const int* __restrict__ labels,
                                               const float* __restrict__ lin_v,
                                               const float* __restrict__ lin_g,
                                               const float* __restrict__ lin_b) {
    __shared__ float swn[GG];
    __shared__ float red[16];
    __shared__ float scs[KK];
    int t = threadIdx.x;
    int warp = t >> 5, lane = t & 31;

    float v = (t < GG) ? lin_v[t] : 0.f;
    float sq = v * v;
    for (int o = 16; o > 0; o >>= 1) sq += __shfl_xor_sync(0xffffffffu, sq, o);
    if (lane == 0) red[warp] = sq;
    __syncthreads();
    if (t == 0) {
        float s = 0.f;
#pragma unroll
        for (int i = 0; i < 16; i++) s += red[i];
        red[0] = 1.f / sqrtf(s);
    }
    __syncthreads();
    if (t < GG) swn[t] = lin_g[0] * v * red[0];
    __syncthreads();

#pragma unroll
    for (int j = 0; j < 2; j++) {
        int c = warp * 2 + j;
        float s = 0.f;
#pragma unroll
        for (int q = 0; q < HH / 32; q++)
            s += g_cemb[c * HH + q * 32 + lane] * swn[DD + q * 32 + lane];
        for (int o = 16; o > 0; o >>= 1) s += __shfl_xor_sync(0xffffffffu, s, o);
        if (lane == 0) scs[c] = s;
    }
    __syncthreads();

    int i = blockIdx.x * 16 + warp;
    const float* xr = x + i * DD;
    float s = 0.f;
#pragma unroll
    for (int q = 0; q < DD / 32; q++)
        s += xr[q * 32 + lane] * swn[q * 32 + lane];
    for (int o = 16; o > 0; o >>= 1) s += __shfl_xor_sync(0xffffffffu, s, o);
    if (lane == 0)
        g_scores[i] = tanhf(s + scs[labels[i]] + lin_b[0]);
}

// ---------------- K5: segment sum + final combine ----------------------------
__global__ void k_tail(const int* __restrict__ labels, float* __restrict__ out) {
    __shared__ float s_sum[KK];
    __shared__ int   slab[NN];
    __shared__ float ssc[NN];
    int tid = threadIdx.x;
#pragma unroll
    for (int r = 0; r < NN / 1024; r++) {
        slab[r * 1024 + tid] = labels[r * 1024 + tid];
        ssc[r * 1024 + tid]  = g_scores[r * 1024 + tid];
    }
    __syncthreads();

    int c = tid >> 5, lane = tid & 31;
    float s = 0.f;
    for (int base = 0; base < NN; base += 32) {
        int lab = slab[base + lane];
        float v = ssc[base + lane];
        if (lab == c) s += v;
    }
    for (int o = 16; o > 0; o >>= 1) s += __shfl_xor_sync(0xffffffffu, s, o);
    if (lane == 0) s_sum[c] = s;
    __syncthreads();

#pragma unroll
    for (int r = 0; r < NN / 1024; r++) {
        int i = r * 1024 + tid;
        float sal = ssc[i] / s_sum[slab[i]];
        float p = fmaxf(0.5f, expf(-(float)(i + 1) * 0.0625f));  // 1/4096^(1/3)=1/16
        out[i] = 0.5f * sal + 0.5f * p;
    }
}

// ---------------- launch ------------------------------------------------------
extern "C" void kernel_launch(void* const* d_in, const int* in_sizes, int n_in,
                              void* d_out, int out_size) {
    const float* x     = (const float*)d_in[0];
    const int*   labels= (const int*)  d_in[1];
    const float* W_ih0 = (const float*)d_in[2];
    const float* W_hh0 = (const float*)d_in[3];
    const float* b_ih0 = (const float*)d_in[4];
    const float* b_hh0 = (const float*)d_in[5];
    const float* W_ih1 = (const float*)d_in[6];
    const float* W_hh1 = (const float*)d_in[7];
    const float* b_ih1 = (const float*)d_in[8];
    const float* b_hh1 = (const float*)d_in[9];
    const float* lin_v = (const float*)d_in[10];
    const float* lin_g = (const float*)d_in[11];
    const float* lin_b = (const float*)d_in[12];
    float* out = (float*)d_out;

    k_prep<<<25, 1024>>>(W_ih0, labels);
    k_xw0<<<NN / TS, GG>>>(x, b_ih0);
    k_gru<<<KK * SUBS, GG>>>(W_hh0, W_ih1, W_hh1, b_ih0, b_hh0, b_ih1, b_hh1);
    k_score<<<NN / 16, 512>>>(x, labels, lin_v, lin_g, lin_b);
    k_tail<<<1, 1024>>>(labels, out);
}

// round 16
// speedup vs baseline: 1.1203x; 1.0027x over previous
#include <cuda_runtime.h>
#include <math.h>
#include <stdint.h>

#define NN 4096
#define KK 32
#define DD 256
#define HH 128
#define GG 384   // 3*H
#define SUBS 4   // CTAs per cluster-sequence

typedef unsigned long long ull;

// ---------------- scratch (__device__ globals, no allocation) ----------------
__device__ int    g_order[NN];
__device__ int    g_len[KK];
__device__ int    g_off[KK];
__device__ float4 g_Wih0T[(DD/4)*GG];
__device__ float  g_xw0[NN*GG];
__device__ float  g_cemb[KK*HH];
__device__ float  g_scores[NN];

// ---------------- PTX helpers ------------------------------------------------
__device__ __forceinline__ uint32_t smem_u32(const void* p) {
    uint32_t a;
    asm("{ .reg .u64 t; cvta.to.shared.u64 t, %1; cvt.u32.u64 %0, t; }"
        : "=r"(a) : "l"(p));
    return a;
}
__device__ __forceinline__ uint32_t mapa_rank(uint32_t laddr, int rank) {
    uint32_t r;
    asm("mapa.shared::cluster.u32 %0, %1, %2;" : "=r"(r) : "r"(laddr), "r"(rank));
    return r;
}
__device__ __forceinline__ void st_async_pre(uint32_t raddr, uint32_t rmbar, float v) {
    uint32_t b = __float_as_uint(v);
    asm volatile("st.async.shared::cluster.mbarrier::complete_tx::bytes.b32 [%0], %1, [%2];"
                 :: "r"(raddr), "r"(b), "r"(rmbar) : "memory");
}
__device__ __forceinline__ void rearm_bar(uint32_t mbar, uint32_t txbytes) {
    asm volatile("mbarrier.arrive.expect_tx.shared::cta.b64 _, [%0], %1;"
                 :: "r"(mbar), "r"(txbytes) : "memory");
}
__device__ __forceinline__ void wait_bar(uint32_t mbar, uint32_t parity) {
    asm volatile(
        "{\n\t.reg .pred P;\n\t"
        "LW%=:\n\t"
        "mbarrier.try_wait.parity.acquire.cta.shared::cta.b64 P, [%0], %1;\n\t"
        "@!P bra LW%=;\n\t}"
        :: "r"(mbar), "r"(parity) : "memory");
}
__device__ __forceinline__ void fma2(ull& d, ull a, ull b) {
    asm("fma.rn.f32x2 %0, %1, %2, %0;" : "+l"(d) : "l"(a), "l"(b));
}
__device__ __forceinline__ float2 unpk(ull v) {
    float2 r;
    asm("mov.b64 {%0, %1}, %2;" : "=f"(r.x), "=f"(r.y) : "l"(v));
    return r;
}
__device__ __forceinline__ float tanha(float x) {
    float y;
    asm("tanh.approx.f32 %0, %1;" : "=f"(y) : "f"(x));
    return y;
}
__device__ __forceinline__ float siga(float x) {
    return fmaf(0.5f, tanha(0.5f * x), 0.5f);
}

// ---------------- K0: fused transpose (blocks 0..23) + order (block 24) -----
__global__ __launch_bounds__(1024) void k_prep(const float* __restrict__ W_ih0,
                                               const int* __restrict__ labels) {
    if (blockIdx.x < 24) {
        int idx = blockIdx.x * 1024 + threadIdx.x;
        int k4 = idx & 63;
        int g  = idx >> 6;
        float4 v = *reinterpret_cast<const float4*>(W_ih0 + g * DD + 4 * k4);
        g_Wih0T[k4 * GG + g] = v;
        return;
    }
    __shared__ int slab[NN];
    __shared__ int s_len[KK];
    __shared__ int s_off[KK];
    int tid = threadIdx.x;
    int c    = tid >> 5;
    int lane = tid & 31;

#pragma unroll
    for (int r = 0; r < NN / 1024; r++)
        slab[r * 1024 + tid] = labels[r * 1024 + tid];
    __syncthreads();

    int count = 0;
    for (int base = 0; base < NN; base += 32) {
        int lab = slab[base + lane];
        unsigned m = __ballot_sync(0xffffffffu, lab == c);
        count += __popc(m);
    }
    if (lane == 0) s_len[c] = count;
    __syncthreads();

    if (c == 0) {
        int len = s_len[lane];
        int off = 0;
        for (int j = 0; j < KK; j++) {
            int lj = __shfl_sync(0xffffffffu, len, j);
            if (j < lane) off += lj;
        }
        s_off[lane] = off;
        g_len[lane] = len;
        g_off[lane] = off;
    }
    __syncthreads();

    int off = s_off[c];
    int cnt = 0;
    for (int base = 0; base < NN; base += 32) {
        int lab = slab[base + lane];
        unsigned m = __ballot_sync(0xffffffffu, lab == c);
        if (lab == c) {
            int p = cnt + __popc(m & ((1u << lane) - 1u));
            g_order[off + p] = base + lane;
        }
        cnt += __popc(m);
    }
}

// ---------------- K2: xw0 = X_gathered @ W_ih0^T + b_ih0 (f32x2, TS=16) -----
#define TS 16
__global__ __launch_bounds__(GG) void k_xw0(const float* __restrict__ x,
                                            const float* __restrict__ b_ih0) {
    __shared__ __align__(16) float shx[TS * DD];
    int g  = threadIdx.x;
    int s0 = blockIdx.x * TS;

    for (int idx = g; idx < TS * DD; idx += GG) {
        int s2 = idx / DD;
        int kk = idx % DD;
        int sent = g_order[s0 + s2];
        shx[idx] = x[sent * DD + kk];
    }
    __syncthreads();

    ull a01[TS], a23[TS];
#pragma unroll
    for (int i = 0; i < TS; i++) { a01[i] = 0ull; a23[i] = 0ull; }

    const ulonglong2* W2 = reinterpret_cast<const ulonglong2*>(g_Wih0T);
    for (int k4 = 0; k4 < DD / 4; k4++) {
        ulonglong2 w = W2[k4 * GG + g];
#pragma unroll
        for (int s2 = 0; s2 < TS; s2++) {
            ulonglong2 xv = *reinterpret_cast<const ulonglong2*>(&shx[s2 * DD + 4 * k4]);
            fma2(a01[s2], w.x, xv.x);
            fma2(a23[s2], w.y, xv.y);
        }
    }
    float b = b_ih0[g];
#pragma unroll
    for (int s2 = 0; s2 < TS; s2++) {
        float2 p = unpk(a01[s2]), q = unpk(a23[s2]);
        g_xw0[(s0 + s2) * GG + g] = (p.x + p.y) + (q.x + q.y) + b;
    }
}

// ---------------- K3: 2-layer GRU, 4-CTA cluster, pipelined layers -----------
// Best-measured config: st.async to all 4 ranks (TX=1024, count=1 barriers),
// pre-mapped mapa bases, producer warps bar.arrive / gate warps bar.sync,
// rearm off the gate critical path (producer thread t==383).
__global__ __launch_bounds__(GG, 1) __cluster_dims__(SUBS, 1, 1)
void k_gru(const float* __restrict__ W_hh0, const float* __restrict__ W_ih1,
           const float* __restrict__ W_hh1,
           const float* __restrict__ b_ih0, const float* __restrict__ b_hh0,
           const float* __restrict__ b_ih1, const float* __restrict__ b_hh1) {
    __shared__ __align__(16) float sh1[2][HH];
    __shared__ __align__(16) float sh2[2][HH];
    __shared__ float sp0[GG];
    __shared__ float sp1[GG];
    __shared__ __align__(8) unsigned long long mbar[2];

    int t   = threadIdx.x;
    int sub = blockIdx.x & (SUBS - 1);
    int c   = blockIdx.x / SUBS;

    // layer-0 role: 4 threads per row, 96 rows
    int q0 = t / 96;
    int i0 = t % 96;
    int g0 = i0 >> 5, e0 = i0 & 31;
    int R0 = 128 * g0 + 32 * sub + e0;

    // layer-1 role: 2 threads per row, 192 rows (96 Wih1 + 96 Whh1)
    int half = t / 192;
    int i1   = t % 192;
    int isW  = (i1 >= 96);
    int r1   = isW ? (i1 - 96) : i1;
    int g1 = r1 >> 5, e1 = r1 & 31;
    int R1 = 128 * g1 + 32 * sub + e1;

    // ---- register-resident weights (f32x2 pairs) ----
    ulonglong2 w0[8];
    const ulonglong2* p0 = reinterpret_cast<const ulonglong2*>(W_hh0 + R0 * HH + 32 * q0);
#pragma unroll
    for (int j = 0; j < 8; j++) w0[j] = p0[j];

    ulonglong2 w1[16];
    const float* Wsrc = isW ? W_hh1 : W_ih1;
    const ulonglong2* p1 = reinterpret_cast<const ulonglong2*>(Wsrc + R1 * HH + 64 * half);
#pragma unroll
    for (int j = 0; j < 16; j++) w1[j] = p1[j];

    // ---- biases: warp0 = layer0 gates, warp1 = layer1 gates ----
    float br_i = 0, bz_i = 0, bn_i = 0, br_h = 0, bz_h = 0, bn_h = 0;
    if (t < 32) {
        int e = 32 * sub + t;
        br_i = b_ih0[e]; bz_i = b_ih0[e + 128]; bn_i = b_ih0[e + 256];
        br_h = b_hh0[e]; bz_h = b_hh0[e + 128]; bn_h = b_hh0[e + 256];
    } else if (t < 64) {
        int e = 32 * sub + (t - 32);
        br_i = b_ih1[e]; bz_i = b_ih1[e + 128]; bn_i = b_ih1[e + 256];
        br_h = b_hh1[e]; bz_h = b_hh1[e + 128]; bn_h = b_hh1[e + 256];
    }

    if (t < HH) { sh1[0][t] = 0.f; sh1[1][t] = 0.f; sh2[0][t] = 0.f; sh2[1][t] = 0.f; }

    uint32_t mb[2];
    mb[0] = smem_u32(&mbar[0]); mb[1] = smem_u32(&mbar[1]);
    const uint32_t TX = 2 * HH * 4;  // 128 h1 + 128 h2 floats per phase
    if (t == 0) {
        asm volatile("mbarrier.init.shared.b64 [%0], 1;" :: "r"(mb[0]) : "memory");
        asm volatile("mbarrier.init.shared.b64 [%0], 1;" :: "r"(mb[1]) : "memory");
        rearm_bar(mb[0], TX); rearm_bar(mb[1], TX);
    }
    asm volatile("fence.proxy.async.shared::cta;" ::: "memory");
    __syncthreads();
    asm volatile("barrier.cluster.arrive.aligned;" ::: "memory");
    asm volatile("barrier.cluster.wait.aligned;" ::: "memory");

    int len   = g_len[c];
    int off   = g_off[c];
    int steps = len > 0 ? len : 1;

    uint32_t sh1a = smem_u32(&sh1[0][0]);
    uint32_t sh2a = smem_u32(&sh2[0][0]);

    // ---- pre-mapped remote bases ----
    uint32_t r_sh1[SUBS], r_sh2[SUBS], r_mb[SUBS];
#pragma unroll
    for (int p = 0; p < SUBS; p++) {
        r_sh1[p] = mapa_rank(sh1a, p);
        r_sh2[p] = mapa_rank(sh2a, p);
        r_mb[p]  = mapa_rank(mb[0], p);
    }

    float h2fin = 0.f;

    for (int s = 0; s <= steps; s++) {
        int rb1 = (s + 1) & 1;   // h1[s-1]
        int wb1 = s & 1;         // h1[s]
        int rb2 = s & 1;         // h2[s-2]
        int wb2 = (s + 1) & 1;   // h2[s-1]
        uint32_t mboff = (uint32_t)((s & 1) * 8);

        // prefetch input gates BEFORE the wait (overlaps L2 latency)
        float xwr = br_i, xwz = bz_i, xwn = bn_i;
        if (t < 32 && s < len) {
            const float* xp = g_xw0 + (off + s) * GG + 32 * sub + t;
            xwr = xp[0]; xwz = xp[128]; xwn = xp[256];
        }

        if (s > 0) {
            wait_bar(mb[(s - 1) & 1], (uint32_t)(((s - 1) >> 1) & 1));
            if (t == 383) rearm_bar(mb[(s - 1) & 1], TX);  // arm iter s+1 (producer)
        }

        // ---- layer 0 matvec over h1[s-1] (f32x2) ----
        {
            ull a01 = 0ull, a23 = 0ull;
            const ulonglong2* hv = reinterpret_cast<const ulonglong2*>(&sh1[rb1][32 * q0]);
#pragma unroll
            for (int j = 0; j < 8; j++) {
                ulonglong2 h = hv[j];
                fma2(a01, w0[j].x, h.x);
                fma2(a23, w0[j].y, h.y);
            }
            float2 p = unpk(a01), q = unpk(a23);
            sp0[t] = (p.x + p.y) + (q.x + q.y);
        }
        // ---- layer 1 matvecs over h1[s-1] / h2[s-2] (f32x2) ----
        {
            const ulonglong2* hv = isW
                ? reinterpret_cast<const ulonglong2*>(&sh2[rb2][64 * half])
                : reinterpret_cast<const ulonglong2*>(&sh1[rb1][64 * half]);
            ull a01 = 0ull, a23 = 0ull;
#pragma unroll
            for (int j = 0; j < 16; j++) {
                ulonglong2 h = hv[j];
                fma2(a01, w1[j].x, h.x);
                fma2(a23, w1[j].y, h.y);
            }
            float2 p = unpk(a01), q = unpk(a23);
            sp1[t] = (p.x + p.y) + (q.x + q.y);
        }

        if (t >= 64) {
            // producers: post arrival, run ahead to next iteration's wait
            asm volatile("bar.arrive 1, 384;" ::: "memory");
            continue;
        }
        // consumers (gate warps): wait for all sp writes
        asm volatile("bar.sync 1, 384;" ::: "memory");

        if (t < 32) {
            float hr = sp0[t]      + sp0[96 + t]  + sp0[192 + t] + sp0[288 + t] + br_h;
            float hz = sp0[32 + t] + sp0[128 + t] + sp0[224 + t] + sp0[320 + t] + bz_h;
            float hn = sp0[64 + t] + sp0[160 + t] + sp0[256 + t] + sp0[352 + t] + bn_h;
            float rg = siga(xwr + hr);
            float zg = siga(xwz + hz);
            float ng = tanha(xwn + rg * hn);
            float h1o = sh1[rb1][32 * sub + t];
            float h1n = (1.f - zg) * ng + zg * h1o;
            uint32_t woff = (uint32_t)(wb1 * HH + 32 * sub + t) * 4u;
#pragma unroll
            for (int p = 0; p < SUBS; p++)
                st_async_pre(r_sh1[p] + woff, r_mb[p] + mboff, h1n);
        } else {
            int e = t - 32;
            float xr = sp1[e]       + sp1[192 + e] + br_i;
            float xz = sp1[32 + e]  + sp1[224 + e] + bz_i;
            float xn = sp1[64 + e]  + sp1[256 + e] + bn_i;
            float hr = sp1[96 + e]  + sp1[288 + e] + br_h;
            float hz = sp1[128 + e] + sp1[320 + e] + bz_h;
            float hn = sp1[160 + e] + sp1[352 + e] + bn_h;
            float rg = siga(xr + hr);
            float zg = siga(xz + hz);
            float ng = tanha(xn + rg * hn);
            float h2o = sh2[rb2][32 * sub + e];
            float h2n = (1.f - zg) * ng + zg * h2o;
            if (s == 0) h2n = 0.f;        // h2[-1] = initial state
            if (s == steps) h2fin = h2n;  // h2[steps-1] = final
            uint32_t woff = (uint32_t)(wb2 * HH + 32 * sub + e) * 4u;
#pragma unroll
            for (int p = 0; p < SUBS; p++)
                st_async_pre(r_sh2[p] + woff, r_mb[p] + mboff, h2n);
        }
    }

    // drain final exchange so no st.async is in flight at exit
    wait_bar(mb[steps & 1], (uint32_t)((steps >> 1) & 1));

    if (t >= 32 && t < 64) g_cemb[c * HH + 32 * sub + (t - 32)] = h2fin;

    asm volatile("barrier.cluster.arrive.aligned;" ::: "memory");
    asm volatile("barrier.cluster.wait.aligned;" ::: "memory");
}

// ---------------- K4: per-sentence scores (wn + cscore computed in-block) ----
__global__ __launch_bounds__(512) void k_score(const float* __restrict__ x,
                                               const int* __restrict__ labels,
                                               const float* __restrict__ lin_v,
                                               const float* __restrict__ lin_g,
                                               const float* __restrict__ lin_b) {
    __shared__ float swn[GG];
    __shared__ float red[16];
    __shared__ float scs[KK];
    int t = threadIdx.x;
    int warp = t >> 5, lane = t & 31;

    float v = (t < GG) ? lin_v[t] : 0.f;
    float sq = v * v;
    for (int o = 16; o > 0; o >>= 1) sq += __shfl_xor_sync(0xffffffffu, sq, o);
    if (lane == 0) red[warp] = sq;
    __syncthreads();
    if (t == 0) {
        float s = 0.f;
#pragma unroll
        for (int i = 0; i < 16; i++) s += red[i];
        red[0] = 1.f / sqrtf(s);
    }
    __syncthreads();
    if (t < GG) swn[t] = lin_g[0] * v * red[0];
    __syncthreads();

#pragma unroll
    for (int j = 0; j < 2; j++) {
        int c = warp * 2 + j;
        float s = 0.f;
#pragma unroll
        for (int q = 0; q < HH / 32; q++)
            s += g_cemb[c * HH + q * 32 + lane] * swn[DD + q * 32 + lane];
        for (int o = 16; o > 0; o >>= 1) s += __shfl_xor_sync(0xffffffffu, s, o);
        if (lane == 0) scs[c] = s;
    }
    __syncthreads();

    int i = blockIdx.x * 16 + warp;
    const float* xr = x + i * DD;
    float s = 0.f;
#pragma unroll
    for (int q = 0; q < DD / 32; q++)
        s += xr[q * 32 + lane] * swn[q * 32 + lane];
    for (int o = 16; o > 0; o >>= 1) s += __shfl_xor_sync(0xffffffffu, s, o);
    if (lane == 0)
        g_scores[i] = tanhf(s + scs[labels[i]] + lin_b[0]);
}

// ---------------- K5: segment sum + final combine ----------------------------
__global__ void k_tail(const int* __restrict__ labels, float* __restrict__ out) {
    __shared__ float s_sum[KK];
    __shared__ int   slab[NN];
    __shared__ float ssc[NN];
    int tid = threadIdx.x;
#pragma unroll
    for (int r = 0; r < NN / 1024; r++) {
        slab[r * 1024 + tid] = labels[r * 1024 + tid];
        ssc[r * 1024 + tid]  = g_scores[r * 1024 + tid];
    }
    __syncthreads();

    int c = tid >> 5, lane = tid & 31;
    float s = 0.f;
    for (int base = 0; base < NN; base += 32) {
        int lab = slab[base + lane];
        float v = ssc[base + lane];
        if (lab == c) s += v;
    }
    for (int o = 16; o > 0; o >>= 1) s += __shfl_xor_sync(0xffffffffu, s, o);
    if (lane == 0) s_sum[c] = s;
    __syncthreads();

#pragma unroll
    for (int r = 0; r < NN / 1024; r++) {
        int i = r * 1024 + tid;
        float sal = ssc[i] / s_sum[slab[i]];
        float p = fmaxf(0.5f, expf(-(float)(i + 1) * 0.0625f));  // 1/4096^(1/3)=1/16
        out[i] = 0.5f * sal + 0.5f * p;
    }
}

// ---------------- launch ------------------------------------------------------
extern "C" void kernel_launch(void* const* d_in, const int* in_sizes, int n_in,
                              void* d_out, int out_size) {
    const float* x     = (const float*)d_in[0];
    const int*   labels= (const int*)  d_in[1];
    const float* W_ih0 = (const float*)d_in[2];
    const float* W_hh0 = (const float*)d_in[3];
    const float* b_ih0 = (const float*)d_in[4];
    const float* b_hh0 = (const float*)d_in[5];
    const float* W_ih1 = (const float*)d_in[6];
    const float* W_hh1 = (const float*)d_in[7];
    const float* b_ih1 = (const float*)d_in[8];
    const float* b_hh1 = (const float*)d_in[9];
    const float* lin_v = (const float*)d_in[10];
    const float* lin_g = (const float*)d_in[11];
    const float* lin_b = (const float*)d_in[12];
    float* out = (float*)d_out;

    k_prep<<<25, 1024>>>(W_ih0, labels);
    k_xw0<<<NN / TS, GG>>>(x, b_ih0);
    k_gru<<<KK * SUBS, GG>>>(W_hh0, W_ih1, W_hh1, b_ih0, b_hh0, b_ih1, b_hh1);
    k_score<<<NN / 16, 512>>>(x, labels, lin_v, lin_g, lin_b);
    k_tail<<<1, 1024>>>(labels, out);
}

// round 17
// speedup vs baseline: 1.1219x; 1.0014x over previous
#include <cuda_runtime.h>
#include <math.h>
#include <stdint.h>

#define NN 4096
#define KK 32
#define DD 256
#define HH 128
#define GG 384   // 3*H
#define SUBS 4   // CTAs per cluster-sequence

typedef unsigned long long ull;

// ---------------- scratch (__device__ globals, no allocation) ----------------
__device__ int    g_order[NN];
__device__ int    g_len[KK];
__device__ int    g_off[KK];
__device__ float4 g_Wih0T[(DD/4)*GG];
__device__ float  g_xw0[NN*GG];
__device__ float  g_cemb[KK*HH];
__device__ float  g_dotx[NN];

// ---------------- PTX helpers ------------------------------------------------
__device__ __forceinline__ uint32_t smem_u32(const void* p) {
    uint32_t a;
    asm("{ .reg .u64 t; cvta.to.shared.u64 t, %1; cvt.u32.u64 %0, t; }"
        : "=r"(a) : "l"(p));
    return a;
}
__device__ __forceinline__ uint32_t mapa_rank(uint32_t laddr, int rank) {
    uint32_t r;
    asm("mapa.shared::cluster.u32 %0, %1, %2;" : "=r"(r) : "r"(laddr), "r"(rank));
    return r;
}
__device__ __forceinline__ void st_async_pre(uint32_t raddr, uint32_t rmbar, float v) {
    uint32_t b = __float_as_uint(v);
    asm volatile("st.async.shared::cluster.mbarrier::complete_tx::bytes.b32 [%0], %1, [%2];"
                 :: "r"(raddr), "r"(b), "r"(rmbar) : "memory");
}
__device__ __forceinline__ void rearm_bar(uint32_t mbar, uint32_t txbytes) {
    asm volatile("mbarrier.arrive.expect_tx.shared::cta.b64 _, [%0], %1;"
                 :: "r"(mbar), "r"(txbytes) : "memory");
}
__device__ __forceinline__ void wait_bar(uint32_t mbar, uint32_t parity) {
    asm volatile(
        "{\n\t.reg .pred P;\n\t"
        "LW%=:\n\t"
        "mbarrier.try_wait.parity.acquire.cta.shared::cta.b64 P, [%0], %1;\n\t"
        "@!P bra LW%=;\n\t}"
        :: "r"(mbar), "r"(parity) : "memory");
}
__device__ __forceinline__ void fma2(ull& d, ull a, ull b) {
    asm("fma.rn.f32x2 %0, %1, %2, %0;" : "+l"(d) : "l"(a), "l"(b));
}
__device__ __forceinline__ float2 unpk(ull v) {
    float2 r;
    asm("mov.b64 {%0, %1}, %2;" : "=f"(r.x), "=f"(r.y) : "l"(v));
    return r;
}
__device__ __forceinline__ float tanha(float x) {
    float y;
    asm("tanh.approx.f32 %0, %1;" : "=f"(y) : "f"(x));
    return y;
}
__device__ __forceinline__ float siga(float x) {
    return fmaf(0.5f, tanha(0.5f * x), 0.5f);
}

// ---------------- K0: fused transpose (blocks 0..23) + order (block 24) -----
__global__ __launch_bounds__(1024) void k_prep(const float* __restrict__ W_ih0,
                                               const int* __restrict__ labels) {
    if (blockIdx.x < 24) {
        int idx = blockIdx.x * 1024 + threadIdx.x;
        int k4 = idx & 63;
        int g  = idx >> 6;
        float4 v = *reinterpret_cast<const float4*>(W_ih0 + g * DD + 4 * k4);
        g_Wih0T[k4 * GG + g] = v;
        return;
    }
    __shared__ int slab[NN];
    __shared__ int s_len[KK];
    __shared__ int s_off[KK];
    int tid = threadIdx.x;
    int c    = tid >> 5;
    int lane = tid & 31;

#pragma unroll
    for (int r = 0; r < NN / 1024; r++)
        slab[r * 1024 + tid] = labels[r * 1024 + tid];
    __syncthreads();

    int count = 0;
    for (int base = 0; base < NN; base += 32) {
        int lab = slab[base + lane];
        unsigned m = __ballot_sync(0xffffffffu, lab == c);
        count += __popc(m);
    }
    if (lane == 0) s_len[c] = count;
    __syncthreads();

    if (c == 0) {
        int len = s_len[lane];
        int off = 0;
        for (int j = 0; j < KK; j++) {
            int lj = __shfl_sync(0xffffffffu, len, j);
            if (j < lane) off += lj;
        }
        s_off[lane] = off;
        g_len[lane] = len;
        g_off[lane] = off;
    }
    __syncthreads();

    int off = s_off[c];
    int cnt = 0;
    for (int base = 0; base < NN; base += 32) {
        int lab = slab[base + lane];
        unsigned m = __ballot_sync(0xffffffffu, lab == c);
        if (lab == c) {
            int p = cnt + __popc(m & ((1u << lane) - 1u));
            g_order[off + p] = base + lane;
        }
        cnt += __popc(m);
    }
}

// ---------------- K2: xw0 + fused x.wn dot (f32x2, TS=16) --------------------
#define TS 16
__global__ __launch_bounds__(GG) void k_xw0(const float* __restrict__ x,
                                            const float* __restrict__ b_ih0,
                                            const float* __restrict__ lin_v,
                                            const float* __restrict__ lin_g) {
    __shared__ __align__(16) float shx[TS * DD];
    __shared__ float swn[DD];
    __shared__ float red[12];
    __shared__ int   ssent[TS];
    int g  = threadIdx.x;
    int warp = g >> 5, lane = g & 31;
    int s0 = blockIdx.x * TS;

    // ---- swn[0:256] = normalized lin_v (norm over all 384) ----
    float v = lin_v[g];
    float sq = v * v;
    for (int o = 16; o > 0; o >>= 1) sq += __shfl_xor_sync(0xffffffffu, sq, o);
    if (lane == 0) red[warp] = sq;
    if (g < TS) ssent[g] = g_order[s0 + g];
    __syncthreads();
    if (g == 0) {
        float s = 0.f;
#pragma unroll
        for (int i = 0; i < 12; i++) s += red[i];
        red[0] = 1.f / sqrtf(s);
    }
    __syncthreads();
    if (g < DD) swn[g] = lin_g[0] * v * red[0];

    for (int idx = g; idx < TS * DD; idx += GG) {
        int s2 = idx / DD;
        int kk = idx % DD;
        int sent = g_order[s0 + s2];
        shx[idx] = x[sent * DD + kk];
    }
    __syncthreads();

    ull a01[TS], a23[TS];
#pragma unroll
    for (int i = 0; i < TS; i++) { a01[i] = 0ull; a23[i] = 0ull; }

    const ulonglong2* W2 = reinterpret_cast<const ulonglong2*>(g_Wih0T);
    for (int k4 = 0; k4 < DD / 4; k4++) {
        ulonglong2 w = W2[k4 * GG + g];
#pragma unroll
        for (int s2 = 0; s2 < TS; s2++) {
            ulonglong2 xv = *reinterpret_cast<const ulonglong2*>(&shx[s2 * DD + 4 * k4]);
            fma2(a01[s2], w.x, xv.x);
            fma2(a23[s2], w.y, xv.y);
        }
    }
    float b = b_ih0[g];
#pragma unroll
    for (int s2 = 0; s2 < TS; s2++) {
        float2 p = unpk(a01[s2]), q = unpk(a23[s2]);
        g_xw0[(s0 + s2) * GG + g] = (p.x + p.y) + (q.x + q.y) + b;
    }

    // ---- fused dot: x[sent] . swn (one warp per sentence) ----
    for (int s2 = warp; s2 < TS; s2 += 12) {
        float s = 0.f;
#pragma unroll
        for (int q = 0; q < DD / 32; q++)
            s += shx[s2 * DD + q * 32 + lane] * swn[q * 32 + lane];
        for (int o = 16; o > 0; o >>= 1) s += __shfl_xor_sync(0xffffffffu, s, o);
        if (lane == 0) g_dotx[ssent[s2]] = s;
    }
}

// ---------------- K3: 2-layer GRU, 4-CTA cluster (banked best config) --------
__global__ __launch_bounds__(GG, 1) __cluster_dims__(SUBS, 1, 1)
void k_gru(const float* __restrict__ W_hh0, const float* __restrict__ W_ih1,
           const float* __restrict__ W_hh1,
           const float* __restrict__ b_ih0, const float* __restrict__ b_hh0,
           const float* __restrict__ b_ih1, const float* __restrict__ b_hh1) {
    __shared__ __align__(16) float sh1[2][HH];
    __shared__ __align__(16) float sh2[2][HH];
    __shared__ float sp0[GG];
    __shared__ float sp1[GG];
    __shared__ __align__(8) unsigned long long mbar[2];

    int t   = threadIdx.x;
    int sub = blockIdx.x & (SUBS - 1);
    int c   = blockIdx.x / SUBS;

    int q0 = t / 96;
    int i0 = t % 96;
    int g0 = i0 >> 5, e0 = i0 & 31;
    int R0 = 128 * g0 + 32 * sub + e0;

    int half = t / 192;
    int i1   = t % 192;
    int isW  = (i1 >= 96);
    int r1   = isW ? (i1 - 96) : i1;
    int g1 = r1 >> 5, e1 = r1 & 31;
    int R1 = 128 * g1 + 32 * sub + e1;

    ulonglong2 w0[8];
    const ulonglong2* p0 = reinterpret_cast<const ulonglong2*>(W_hh0 + R0 * HH + 32 * q0);
#pragma unroll
    for (int j = 0; j < 8; j++) w0[j] = p0[j];

    ulonglong2 w1[16];
    const float* Wsrc = isW ? W_hh1 : W_ih1;
    const ulonglong2* p1 = reinterpret_cast<const ulonglong2*>(Wsrc + R1 * HH + 64 * half);
#pragma unroll
    for (int j = 0; j < 16; j++) w1[j] = p1[j];

    float br_i = 0, bz_i = 0, bn_i = 0, br_h = 0, bz_h = 0, bn_h = 0;
    if (t < 32) {
        int e = 32 * sub + t;
        br_i = b_ih0[e]; bz_i = b_ih0[e + 128]; bn_i = b_ih0[e + 256];
        br_h = b_hh0[e]; bz_h = b_hh0[e + 128]; bn_h = b_hh0[e + 256];
    } else if (t < 64) {
        int e = 32 * sub + (t - 32);
        br_i = b_ih1[e]; bz_i = b_ih1[e + 128]; bn_i = b_ih1[e + 256];
        br_h = b_hh1[e]; bz_h = b_hh1[e + 128]; bn_h = b_hh1[e + 256];
    }

    if (t < HH) { sh1[0][t] = 0.f; sh1[1][t] = 0.f; sh2[0][t] = 0.f; sh2[1][t] = 0.f; }

    uint32_t mb[2];
    mb[0] = smem_u32(&mbar[0]); mb[1] = smem_u32(&mbar[1]);
    const uint32_t TX = 2 * HH * 4;  // 128 h1 + 128 h2 floats per phase
    if (t == 0) {
        asm volatile("mbarrier.init.shared.b64 [%0], 1;" :: "r"(mb[0]) : "memory");
        asm volatile("mbarrier.init.shared.b64 [%0], 1;" :: "r"(mb[1]) : "memory");
        rearm_bar(mb[0], TX); rearm_bar(mb[1], TX);
    }
    asm volatile("fence.proxy.async.shared::cta;" ::: "memory");
    __syncthreads();
    asm volatile("barrier.cluster.arrive.aligned;" ::: "memory");
    asm volatile("barrier.cluster.wait.aligned;" ::: "memory");

    int len   = g_len[c];
    int off   = g_off[c];
    int steps = len > 0 ? len : 1;

    uint32_t sh1a = smem_u32(&sh1[0][0]);
    uint32_t sh2a = smem_u32(&sh2[0][0]);

    uint32_t r_sh1[SUBS], r_sh2[SUBS], r_mb[SUBS];
#pragma unroll
    for (int p = 0; p < SUBS; p++) {
        r_sh1[p] = mapa_rank(sh1a, p);
        r_sh2[p] = mapa_rank(sh2a, p);
        r_mb[p]  = mapa_rank(mb[0], p);
    }

    float h2fin = 0.f;

    for (int s = 0; s <= steps; s++) {
        int rb1 = (s + 1) & 1;   // h1[s-1]
        int wb1 = s & 1;         // h1[s]
        int rb2 = s & 1;         // h2[s-2]
        int wb2 = (s + 1) & 1;   // h2[s-1]
        uint32_t mboff = (uint32_t)((s & 1) * 8);

        float xwr = br_i, xwz = bz_i, xwn = bn_i;
        if (t < 32 && s < len) {
            const float* xp = g_xw0 + (off + s) * GG + 32 * sub + t;
            xwr = xp[0]; xwz = xp[128]; xwn = xp[256];
        }

        if (s > 0) {
            wait_bar(mb[(s - 1) & 1], (uint32_t)(((s - 1) >> 1) & 1));
            if (t == 383) rearm_bar(mb[(s - 1) & 1], TX);  // arm iter s+1 (producer)
        }

        {
            ull a01 = 0ull, a23 = 0ull;
            const ulonglong2* hv = reinterpret_cast<const ulonglong2*>(&sh1[rb1][32 * q0]);
#pragma unroll
            for (int j = 0; j < 8; j++) {
                ulonglong2 h = hv[j];
                fma2(a01, w0[j].x, h.x);
                fma2(a23, w0[j].y, h.y);
            }
            float2 p = unpk(a01), q = unpk(a23);
            sp0[t] = (p.x + p.y) + (q.x + q.y);
        }
        {
            const ulonglong2* hv = isW
                ? reinterpret_cast<const ulonglong2*>(&sh2[rb2][64 * half])
                : reinterpret_cast<const ulonglong2*>(&sh1[rb1][64 * half]);
            ull a01 = 0ull, a23 = 0ull;
#pragma unroll
            for (int j = 0; j < 16; j++) {
                ulonglong2 h = hv[j];
                fma2(a01, w1[j].x, h.x);
                fma2(a23, w1[j].y, h.y);
            }
            float2 p = unpk(a01), q = unpk(a23);
            sp1[t] = (p.x + p.y) + (q.x + q.y);
        }

        if (t >= 64) {
            asm volatile("bar.arrive 1, 384;" ::: "memory");
            continue;
        }
        asm volatile("bar.sync 1, 384;" ::: "memory");

        if (t < 32) {
            float hr = sp0[t]      + sp0[96 + t]  + sp0[192 + t] + sp0[288 + t] + br_h;
            float hz = sp0[32 + t] + sp0[128 + t] + sp0[224 + t] + sp0[320 + t] + bz_h;
            float hn = sp0[64 + t] + sp0[160 + t] + sp0[256 + t] + sp0[352 + t] + bn_h;
            float rg = siga(xwr + hr);
            float zg = siga(xwz + hz);
            float ng = tanha(xwn + rg * hn);
            float h1o = sh1[rb1][32 * sub + t];
            float h1n = (1.f - zg) * ng + zg * h1o;
            uint32_t woff = (uint32_t)(wb1 * HH + 32 * sub + t) * 4u;
#pragma unroll
            for (int p = 0; p < SUBS; p++)
                st_async_pre(r_sh1[p] + woff, r_mb[p] + mboff, h1n);
        } else {
            int e = t - 32;
            float xr = sp1[e]       + sp1[192 + e] + br_i;
            float xz = sp1[32 + e]  + sp1[224 + e] + bz_i;
            float xn = sp1[64 + e]  + sp1[256 + e] + bn_i;
            float hr = sp1[96 + e]  + sp1[288 + e] + br_h;
            float hz = sp1[128 + e] + sp1[320 + e] + bz_h;
            float hn = sp1[160 + e] + sp1[352 + e] + bn_h;
            float rg = siga(xr + hr);
            float zg = siga(xz + hz);
            float ng = tanha(xn + rg * hn);
            float h2o = sh2[rb2][32 * sub + e];
            float h2n = (1.f - zg) * ng + zg * h2o;
            if (s == 0) h2n = 0.f;        // h2[-1] = initial state
            if (s == steps) h2fin = h2n;  // h2[steps-1] = final
            uint32_t woff = (uint32_t)(wb2 * HH + 32 * sub + e) * 4u;
#pragma unroll
            for (int p = 0; p < SUBS; p++)
                st_async_pre(r_sh2[p] + woff, r_mb[p] + mboff, h2n);
        }
    }

    wait_bar(mb[steps & 1], (uint32_t)((steps >> 1) & 1));

    if (t >= 32 && t < 64) g_cemb[c * HH + 32 * sub + (t - 32)] = h2fin;

    asm volatile("barrier.cluster.arrive.aligned;" ::: "memory");
    asm volatile("barrier.cluster.wait.aligned;" ::: "memory");
}

// ---------------- K4: final — cscore + scores + segment sum + combine --------
__global__ __launch_bounds__(1024) void k_fin(const int* __restrict__ labels,
                                              const float* __restrict__ lin_v,
                                              const float* __restrict__ lin_g,
                                              const float* __restrict__ lin_b,
                                              float* __restrict__ out) {
    __shared__ float swn[GG];
    __shared__ float red[32];
    __shared__ float scs[KK];
    __shared__ float s_sum[KK];
    __shared__ int   slab[NN];
    __shared__ float ssc[NN];
    int t = threadIdx.x;
    int warp = t >> 5, lane = t & 31;

    // weight-norm (384 values over 32 warps; upper warps contribute 0)
    float v = (t < GG) ? lin_v[t] : 0.f;
    float sq = v * v;
    for (int o = 16; o > 0; o >>= 1) sq += __shfl_xor_sync(0xffffffffu, sq, o);
    if (lane == 0) red[warp] = sq;
#pragma unroll
    for (int r = 0; r < NN / 1024; r++)
        slab[r * 1024 + t] = labels[r * 1024 + t];
    __syncthreads();
    if (t == 0) {
        float s = 0.f;
#pragma unroll
        for (int i = 0; i < 32; i++) s += red[i];
        red[0] = 1.f / sqrtf(s);
    }
    __syncthreads();
    if (t < GG) swn[t] = lin_g[0] * v * red[0];
    __syncthreads();

    // per-cluster scores: warp w -> cluster w
    {
        int c = warp;
        float s = 0.f;
#pragma unroll
        for (int q = 0; q < HH / 32; q++)
            s += g_cemb[c * HH + q * 32 + lane] * swn[DD + q * 32 + lane];
        for (int o = 16; o > 0; o >>= 1) s += __shfl_xor_sync(0xffffffffu, s, o);
        if (lane == 0) scs[c] = s;
    }
    __syncthreads();

    // sentence scores from fused dotx
    float lb = lin_b[0];
#pragma unroll
    for (int r = 0; r < NN / 1024; r++) {
        int i = r * 1024 + t;
        ssc[i] = tanhf(g_dotx[i] + scs[slab[i]] + lb);
    }
    __syncthreads();

    // segment sum: warp c over strided lanes (same order as before)
    {
        int c = warp;
        float s = 0.f;
        for (int base = 0; base < NN; base += 32) {
            int lab = slab[base + lane];
            float vv = ssc[base + lane];
            if (lab == c) s += vv;
        }
        for (int o = 16; o > 0; o >>= 1) s += __shfl_xor_sync(0xffffffffu, s, o);
        if (lane == 0) s_sum[c] = s;
    }
    __syncthreads();

#pragma unroll
    for (int r = 0; r < NN / 1024; r++) {
        int i = r * 1024 + t;
        float sal = ssc[i] / s_sum[slab[i]];
        float p = fmaxf(0.5f, expf(-(float)(i + 1) * 0.0625f));  // 1/4096^(1/3)=1/16
        out[i] = 0.5f * sal + 0.5f * p;
    }
}

// ---------------- launch ------------------------------------------------------
extern "C" void kernel_launch(void* const* d_in, const int* in_sizes, int n_in,
                              void* d_out, int out_size) {
    const float* x     = (const float*)d_in[0];
    const int*   labels= (const int*)  d_in[1];
    const float* W_ih0 = (const float*)d_in[2];
    const float* W_hh0 = (const float*)d_in[3];
    const float* b_ih0 = (const float*)d_in[4];
    const float* b_hh0 = (const float*)d_in[5];
    const float* W_ih1 = (const float*)d_in[6];
    const float* W_hh1 = (const float*)d_in[7];
    const float* b_ih1 = (const float*)d_in[8];
    const float* b_hh1 = (const float*)d_in[9];
    const float* lin_v = (const float*)d_in[10];
    const float* lin_g = (const float*)d_in[11];
    const float* lin_b = (const float*)d_in[12];
    float* out = (float*)d_out;

    k_prep<<<25, 1024>>>(W_ih0, labels);
    k_xw0<<<NN / TS, GG>>>(x, b_ih0, lin_v, lin_g);
    k_gru<<<KK * SUBS, GG>>>(W_hh0, W_ih1, W_hh1, b_ih0, b_hh0, b_ih1, b_hh1);
    k_fin<<<1, 1024>>>(labels, lin_v, lin_g, lin_b, out);
}